// round 1
// baseline (speedup 1.0000x reference)
#include <cuda_runtime.h>

// ---------------- problem constants ----------------
// x: [16, 64, 64, 64]  (B, C, H, W), N = 4096, M = 1024
#define Bv 16
#define Cv 64
#define Nv 4096
#define Mv 1024

typedef unsigned long long ULL;

// ---------------- packed f32x2 helpers (sm_100+ PTX) ----------------
__device__ __forceinline__ ULL f2_mul(ULL a, ULL b) {
    ULL d; asm("mul.rn.f32x2 %0, %1, %2;" : "=l"(d) : "l"(a), "l"(b)); return d;
}
__device__ __forceinline__ ULL f2_fma(ULL a, ULL b, ULL c) {
    ULL d; asm("fma.rn.f32x2 %0, %1, %2, %3;" : "=l"(d) : "l"(a), "l"(b), "l"(c)); return d;
}
__device__ __forceinline__ ULL f2_pack(float lo, float hi) {
    ULL r;
    asm("mov.b64 %0, {%1, %2};" : "=l"(r)
        : "r"(__float_as_uint(lo)), "r"(__float_as_uint(hi)));
    return r;
}
__device__ __forceinline__ float2 f2_unpack(ULL v) {
    unsigned lo, hi;
    asm("mov.b64 {%0, %1}, %2;" : "=r"(lo), "=r"(hi) : "l"(v));
    return make_float2(__uint_as_float(lo), __uint_as_float(hi));
}

// ---------------- scratch (device globals; no allocation allowed) ----------------
__device__ float d_theta[Bv * Nv * 8];   // [b][n][k]  (k contiguous)  2 MB
__device__ float d_phi  [Bv * Mv * 8];   // [b][m][k]                 0.5 MB
__device__ float d_g    [Bv * Mv * 32];  // [b][m][j]                 2 MB

// ======================================================================
// Kernel A1: theta = W_theta @ x   -> d_theta[b][n][0..7]
// grid (16, B), 256 threads; one thread per n.
// ======================================================================
__global__ void theta_kernel(const float* __restrict__ x,
                             const float* __restrict__ Wth) {
    __shared__ float Ws[8 * 64];
    int tid = threadIdx.x;
    for (int i = tid; i < 512; i += 256) Ws[i] = Wth[i];
    __syncthreads();

    int b = blockIdx.y;
    int n = blockIdx.x * 256 + tid;
    const float* xp = x + ((size_t)b * Cv) * Nv + n;

    float acc[8];
#pragma unroll
    for (int k = 0; k < 8; k++) acc[k] = 0.f;

#pragma unroll 8
    for (int c = 0; c < 64; c++) {
        float xv = xp[(size_t)c * Nv];
#pragma unroll
        for (int k = 0; k < 8; k++) acc[k] = fmaf(Ws[k * 64 + c], xv, acc[k]);
    }

    float* dst = d_theta + ((size_t)(b * Nv + n)) * 8;
    ((float4*)dst)[0] = make_float4(acc[0], acc[1], acc[2], acc[3]);
    ((float4*)dst)[1] = make_float4(acc[4], acc[5], acc[6], acc[7]);
}

// ======================================================================
// Kernel A2: phi = maxpool(W_phi @ x), g = maxpool(W_g @ x)
// grid (8, B), 128 threads; one thread per pooled position m.
// W transposed in SMEM so per-c reads are float4.
// ======================================================================
__global__ void phig_kernel(const float* __restrict__ x,
                            const float* __restrict__ Wphi,
                            const float* __restrict__ Wg) {
    __shared__ float Wpt[64 * 8];    // [c][k]
    __shared__ float Wgt[64 * 32];   // [c][j]
    int tid = threadIdx.x;
    for (int i = tid; i < 512; i += 128) {
        int k = i >> 6, c = i & 63;
        Wpt[c * 8 + k] = Wphi[i];
    }
    for (int i = tid; i < 2048; i += 128) {
        int j = i >> 6, c = i & 63;
        Wgt[c * 32 + j] = Wg[i];
    }
    __syncthreads();

    int b = blockIdx.y;
    int m = blockIdx.x * 128 + tid;
    int h2 = m >> 5, w2 = m & 31;
    int n0 = (h2 << 1) * 64 + (w2 << 1);
    const float* xb = x + ((size_t)b * Cv) * Nv;

    float bp[8], bg[32];
#pragma unroll
    for (int k = 0; k < 8; k++) bp[k] = -3.4e38f;
#pragma unroll
    for (int j = 0; j < 32; j++) bg[j] = -3.4e38f;

#pragma unroll 1
    for (int p = 0; p < 4; p++) {
        int np = n0 + (p >> 1) * 64 + (p & 1);
        const float* xp = xb + np;
        float ap[8], ag[32];
#pragma unroll
        for (int k = 0; k < 8; k++) ap[k] = 0.f;
#pragma unroll
        for (int j = 0; j < 32; j++) ag[j] = 0.f;

#pragma unroll 4
        for (int c = 0; c < 64; c++) {
            float xv = xp[(size_t)c * Nv];
            const float4* wp = (const float4*)&Wpt[c * 8];
            float4 w0 = wp[0], w1 = wp[1];
            ap[0] = fmaf(w0.x, xv, ap[0]); ap[1] = fmaf(w0.y, xv, ap[1]);
            ap[2] = fmaf(w0.z, xv, ap[2]); ap[3] = fmaf(w0.w, xv, ap[3]);
            ap[4] = fmaf(w1.x, xv, ap[4]); ap[5] = fmaf(w1.y, xv, ap[5]);
            ap[6] = fmaf(w1.z, xv, ap[6]); ap[7] = fmaf(w1.w, xv, ap[7]);
            const float4* wg = (const float4*)&Wgt[c * 32];
#pragma unroll
            for (int q = 0; q < 8; q++) {
                float4 wv = wg[q];
                ag[q * 4 + 0] = fmaf(wv.x, xv, ag[q * 4 + 0]);
                ag[q * 4 + 1] = fmaf(wv.y, xv, ag[q * 4 + 1]);
                ag[q * 4 + 2] = fmaf(wv.z, xv, ag[q * 4 + 2]);
                ag[q * 4 + 3] = fmaf(wv.w, xv, ag[q * 4 + 3]);
            }
        }
#pragma unroll
        for (int k = 0; k < 8; k++) bp[k] = fmaxf(bp[k], ap[k]);
#pragma unroll
        for (int j = 0; j < 32; j++) bg[j] = fmaxf(bg[j], ag[j]);
    }

    float* pd = d_phi + ((size_t)(b * Mv + m)) * 8;
    ((float4*)pd)[0] = make_float4(bp[0], bp[1], bp[2], bp[3]);
    ((float4*)pd)[1] = make_float4(bp[4], bp[5], bp[6], bp[7]);
    float* gd = d_g + ((size_t)(b * Mv + m)) * 32;
#pragma unroll
    for (int q = 0; q < 8; q++)
        ((float4*)gd)[q] = make_float4(bg[q * 4], bg[q * 4 + 1], bg[q * 4 + 2], bg[q * 4 + 3]);
}

// ======================================================================
// Kernel B: fused attention + epilogue.
// grid (16, B), 256 threads, one query per thread.
// SMEM: phi [1024x8] (32KB) + g tile [256x32] (32KB) + W_attn (8KB) = 72KB.
// All lanes walk the same m -> every LDS is a broadcast (conflict-free).
// Scores are tiny (~N(0,0.2)) so sum-exp without running max is safe in fp32.
// ======================================================================
#define MT 256
__global__ void __launch_bounds__(256, 2)
attn_kernel(const float* __restrict__ x,
            const float* __restrict__ Wattn,
            const float* __restrict__ sigma,
            float* __restrict__ out) {
    extern __shared__ float smem[];
    float* phi_s = smem;            // 8192 floats
    float* g_s   = smem + 8192;     // 8192 floats
    float* wa_s  = smem + 16384;    // 2048 floats

    int tid = threadIdx.x;
    int b = blockIdx.y;
    int n = blockIdx.x * 256 + tid;

    {
        const float4* src = (const float4*)(d_phi + (size_t)b * (Mv * 8));
        float4* dst = (float4*)phi_s;
        for (int i = tid; i < 2048; i += 256) dst[i] = src[i];
        for (int i = tid; i < 2048; i += 256) wa_s[i] = Wattn[i];
    }

    ULL th0, th1, th2, th3;
    {
        const ulonglong2* tp =
            (const ulonglong2*)(d_theta + ((size_t)(b * Nv + n)) * 8);
        ulonglong2 a = tp[0], c = tp[1];
        th0 = a.x; th1 = a.y; th2 = c.x; th3 = c.y;
    }

    ULL acc[16];
#pragma unroll
    for (int i = 0; i < 16; i++) acc[i] = 0ULL;
    float lsum = 0.f;

    const ulonglong2* phi_u = (const ulonglong2*)phi_s;
    const float4* g_glob = (const float4*)(d_g + (size_t)b * (Mv * 32));

    for (int mt = 0; mt < Mv; mt += MT) {
        __syncthreads();
        {
            float4* gd = (float4*)g_s;
            const float4* gs = g_glob + (size_t)mt * 8;
            for (int i = tid; i < MT * 8; i += 256) gd[i] = gs[i];
        }
        __syncthreads();
        const ulonglong2* gu = (const ulonglong2*)g_s;

#pragma unroll 4
        for (int mm = 0; mm < MT; mm++) {
            int m = mt + mm;
            ulonglong2 p0 = phi_u[m * 2 + 0];
            ulonglong2 p1 = phi_u[m * 2 + 1];
            ULL s2 = f2_mul(th0, p0.x);
            s2 = f2_fma(th1, p0.y, s2);
            s2 = f2_fma(th2, p1.x, s2);
            s2 = f2_fma(th3, p1.y, s2);
            float2 sf = f2_unpack(s2);
            float pw = __expf(sf.x + sf.y);
            lsum += pw;
            ULL pp = f2_pack(pw, pw);
            const ulonglong2* gm = gu + (size_t)mm * 8;
#pragma unroll
            for (int jj = 0; jj < 8; jj++) {
                ulonglong2 gv = gm[jj];
                acc[jj * 2 + 0] = f2_fma(pp, gv.x, acc[jj * 2 + 0]);
                acc[jj * 2 + 1] = f2_fma(pp, gv.y, acc[jj * 2 + 1]);
            }
        }
    }

    // epilogue: out[co] = x[co] + sigma * (1/lsum) * sum_j Wattn[co][j]*acc[j]
    float sg = sigma[0] / lsum;
    const float* xp = x + ((size_t)b * Cv) * Nv + n;
    float* op = out + ((size_t)b * Cv) * Nv + n;
    const ulonglong2* wa_u = (const ulonglong2*)wa_s;

#pragma unroll 4
    for (int co = 0; co < 64; co++) {
        const ulonglong2* wr = wa_u + (size_t)co * 8;
        ULL d2 = 0ULL;
#pragma unroll
        for (int jj = 0; jj < 8; jj++) {
            ulonglong2 wv = wr[jj];
            d2 = f2_fma(acc[jj * 2 + 0], wv.x, d2);
            d2 = f2_fma(acc[jj * 2 + 1], wv.y, d2);
        }
        float2 df = f2_unpack(d2);
        op[(size_t)co * Nv] = xp[(size_t)co * Nv] + sg * (df.x + df.y);
    }
}

// ======================================================================
// launch
// ======================================================================
extern "C" void kernel_launch(void* const* d_in, const int* in_sizes, int n_in,
                              void* d_out, int out_size) {
    const float* x     = (const float*)d_in[0];
    const float* Wth   = (const float*)d_in[1];
    const float* Wphi  = (const float*)d_in[2];
    const float* Wg    = (const float*)d_in[3];
    const float* Wattn = (const float*)d_in[4];
    const float* sigma = (const float*)d_in[5];
    float* out = (float*)d_out;

    cudaFuncSetAttribute(attn_kernel,
                         cudaFuncAttributeMaxDynamicSharedMemorySize, 73728);

    theta_kernel<<<dim3(16, Bv), 256>>>(x, Wth);
    phig_kernel<<<dim3(8, Bv), 128>>>(x, Wphi, Wg);
    attn_kernel<<<dim3(16, Bv), 256, 73728>>>(x, Wattn, sigma, out);
}

// round 2
// speedup vs baseline: 1.1255x; 1.1255x over previous
#include <cuda_runtime.h>

// ---------------- problem constants ----------------
#define Bv 16
#define Cv 64
#define Nv 4096
#define Mv 1024
#define LN2R 1.4426950408889634f

typedef unsigned long long ULL;

// ---------------- packed f32x2 helpers (sm_100+ PTX) ----------------
__device__ __forceinline__ ULL f2_mul(ULL a, ULL b) {
    ULL d; asm("mul.rn.f32x2 %0, %1, %2;" : "=l"(d) : "l"(a), "l"(b)); return d;
}
__device__ __forceinline__ ULL f2_fma(ULL a, ULL b, ULL c) {
    ULL d; asm("fma.rn.f32x2 %0, %1, %2, %3;" : "=l"(d) : "l"(a), "l"(b), "l"(c)); return d;
}
__device__ __forceinline__ ULL f2_pack(float lo, float hi) {
    ULL r;
    asm("mov.b64 %0, {%1, %2};" : "=l"(r)
        : "r"(__float_as_uint(lo)), "r"(__float_as_uint(hi)));
    return r;
}
__device__ __forceinline__ float2 f2_unpack(ULL v) {
    unsigned lo, hi;
    asm("mov.b64 {%0, %1}, %2;" : "=r"(lo), "=r"(hi) : "l"(v));
    return make_float2(__uint_as_float(lo), __uint_as_float(hi));
}
__device__ __forceinline__ float ex2(float x) {
    float r; asm("ex2.approx.f32 %0, %1;" : "=f"(r) : "f"(x)); return r;
}

// ---------------- scratch (device globals) ----------------
__device__ float d_theta[Bv * Nv * 8];   // [b][n][k], pre-scaled by 1/ln2
__device__ float d_phi  [Bv * Mv * 8];   // [b][m][k]
__device__ float d_g    [Bv * Mv * 32];  // [b][m][j]

// ======================================================================
// prep_kernel: fused theta (blocks 0..15) + phi/g (blocks 16..23).
// 256 threads. theta: 1 n per thread, c-loop MLP=16.
// phig: pool pixels split across 2 thread-halves, smem max-reduce.
// ======================================================================
__global__ void __launch_bounds__(256)
prep_kernel(const float* __restrict__ x,
            const float* __restrict__ Wth,
            const float* __restrict__ Wphi,
            const float* __restrict__ Wg) {
    __shared__ float sm[512 + 2048 + 128 * 41];
    int tid = threadIdx.x;
    int b = blockIdx.y;

    if (blockIdx.x < 16) {
        // ---------------- theta path ----------------
        float* Ws = sm;
        for (int i = tid; i < 512; i += 256) Ws[i] = Wth[i];
        __syncthreads();

        int n = blockIdx.x * 256 + tid;
        const float* xp = x + ((size_t)b * Cv) * Nv + n;

        float acc[8];
#pragma unroll
        for (int k = 0; k < 8; k++) acc[k] = 0.f;

#pragma unroll
        for (int cc = 0; cc < 64; cc += 16) {
            float xv[16];
#pragma unroll
            for (int u = 0; u < 16; u++) xv[u] = xp[(size_t)(cc + u) * Nv];
#pragma unroll
            for (int u = 0; u < 16; u++) {
#pragma unroll
                for (int k = 0; k < 8; k++)
                    acc[k] = fmaf(Ws[k * 64 + cc + u], xv[u], acc[k]);
            }
        }
        float* dst = d_theta + ((size_t)(b * Nv + n)) * 8;
        ((float4*)dst)[0] = make_float4(acc[0] * LN2R, acc[1] * LN2R,
                                        acc[2] * LN2R, acc[3] * LN2R);
        ((float4*)dst)[1] = make_float4(acc[4] * LN2R, acc[5] * LN2R,
                                        acc[6] * LN2R, acc[7] * LN2R);
    } else {
        // ---------------- phi/g path ----------------
        float* Wpt = sm;          // [c][k]  512
        float* Wgt = sm + 512;    // [c][j]  2048
        float* red = sm + 2560;   // [128][41]
        for (int i = tid; i < 512; i += 256) {
            int k = i >> 6, c = i & 63;
            Wpt[c * 8 + k] = Wphi[i];
        }
        for (int i = tid; i < 2048; i += 256) {
            int j = i >> 6, c = i & 63;
            Wgt[c * 32 + j] = Wg[i];
        }
        __syncthreads();

        int lm = tid & 127, half = tid >> 7;
        int m = (blockIdx.x - 16) * 128 + lm;
        int h2 = m >> 5, w2 = m & 31;
        int n0 = ((h2 << 1) + half) * 64 + (w2 << 1);   // half selects pool row
        const float* xb = x + ((size_t)b * Cv) * Nv;

        float bp[8], bg[32];
#pragma unroll
        for (int k = 0; k < 8; k++) bp[k] = -3.4e38f;
#pragma unroll
        for (int j = 0; j < 32; j++) bg[j] = -3.4e38f;

#pragma unroll 1
        for (int p = 0; p < 2; p++) {
            const float* xp = xb + n0 + p;
            float ap[8], ag[32];
#pragma unroll
            for (int k = 0; k < 8; k++) ap[k] = 0.f;
#pragma unroll
            for (int j = 0; j < 32; j++) ag[j] = 0.f;

#pragma unroll 8
            for (int c = 0; c < 64; c++) {
                float xv = xp[(size_t)c * Nv];
                const float4* wp = (const float4*)&Wpt[c * 8];
                float4 w0 = wp[0], w1 = wp[1];
                ap[0] = fmaf(w0.x, xv, ap[0]); ap[1] = fmaf(w0.y, xv, ap[1]);
                ap[2] = fmaf(w0.z, xv, ap[2]); ap[3] = fmaf(w0.w, xv, ap[3]);
                ap[4] = fmaf(w1.x, xv, ap[4]); ap[5] = fmaf(w1.y, xv, ap[5]);
                ap[6] = fmaf(w1.z, xv, ap[6]); ap[7] = fmaf(w1.w, xv, ap[7]);
                const float4* wg = (const float4*)&Wgt[c * 32];
#pragma unroll
                for (int q = 0; q < 8; q++) {
                    float4 wv = wg[q];
                    ag[q * 4 + 0] = fmaf(wv.x, xv, ag[q * 4 + 0]);
                    ag[q * 4 + 1] = fmaf(wv.y, xv, ag[q * 4 + 1]);
                    ag[q * 4 + 2] = fmaf(wv.z, xv, ag[q * 4 + 2]);
                    ag[q * 4 + 3] = fmaf(wv.w, xv, ag[q * 4 + 3]);
                }
            }
#pragma unroll
            for (int k = 0; k < 8; k++) bp[k] = fmaxf(bp[k], ap[k]);
#pragma unroll
            for (int j = 0; j < 32; j++) bg[j] = fmaxf(bg[j], ag[j]);
        }

        if (half) {
            float* r = red + lm * 41;
#pragma unroll
            for (int k = 0; k < 8; k++) r[k] = bp[k];
#pragma unroll
            for (int j = 0; j < 32; j++) r[8 + j] = bg[j];
        }
        __syncthreads();
        if (!half) {
            const float* r = red + lm * 41;
#pragma unroll
            for (int k = 0; k < 8; k++) bp[k] = fmaxf(bp[k], r[k]);
#pragma unroll
            for (int j = 0; j < 32; j++) bg[j] = fmaxf(bg[j], r[8 + j]);

            float* pd = d_phi + ((size_t)(b * Mv + m)) * 8;
            ((float4*)pd)[0] = make_float4(bp[0], bp[1], bp[2], bp[3]);
            ((float4*)pd)[1] = make_float4(bp[4], bp[5], bp[6], bp[7]);
            float* gd = d_g + ((size_t)(b * Mv + m)) * 32;
#pragma unroll
            for (int q = 0; q < 8; q++)
                ((float4*)gd)[q] = make_float4(bg[q * 4 + 0], bg[q * 4 + 1],
                                               bg[q * 4 + 2], bg[q * 4 + 3]);
        }
    }
}

// ======================================================================
// attn_kernel: 128 threads, 2 queries/thread (n and n+128).
// SMEM: phi 32KB + g tile 32KB + W_attn 8KB = 72KB; 2 CTAs/SM.
// All lanes walk the same m -> every LDS is a broadcast.
// ======================================================================
#define MT 256
__global__ void __launch_bounds__(128, 2)
attn_kernel(const float* __restrict__ x,
            const float* __restrict__ Wattn,
            const float* __restrict__ sigma,
            float* __restrict__ out) {
    extern __shared__ float smem[];
    float* phi_s = smem;            // 8192 floats
    float* g_s   = smem + 8192;     // 8192 floats
    float* wa_s  = smem + 16384;    // 2048 floats

    int tid = threadIdx.x;
    int b = blockIdx.y;
    int n0 = blockIdx.x * 256 + tid;
    int n1 = n0 + 128;

    {
        const float4* src = (const float4*)(d_phi + (size_t)b * (Mv * 8));
        float4* dst = (float4*)phi_s;
        for (int i = tid; i < 2048; i += 128) dst[i] = src[i];
        for (int i = tid; i < 2048; i += 128) wa_s[i] = Wattn[i];
    }

    ULL tA0, tA1, tA2, tA3, tB0, tB1, tB2, tB3;
    {
        const ulonglong2* tp =
            (const ulonglong2*)(d_theta + ((size_t)(b * Nv + n0)) * 8);
        ulonglong2 a = tp[0], c = tp[1];
        tA0 = a.x; tA1 = a.y; tA2 = c.x; tA3 = c.y;
        const ulonglong2* tq =
            (const ulonglong2*)(d_theta + ((size_t)(b * Nv + n1)) * 8);
        ulonglong2 e = tq[0], f = tq[1];
        tB0 = e.x; tB1 = e.y; tB2 = f.x; tB3 = f.y;
    }

    ULL acc0[16], acc1[16];
#pragma unroll
    for (int i = 0; i < 16; i++) { acc0[i] = 0ULL; acc1[i] = 0ULL; }
    float lsum0 = 0.f, lsum1 = 0.f;

    const ulonglong2* phi_u = (const ulonglong2*)phi_s;
    const float4* g_glob = (const float4*)(d_g + (size_t)b * (Mv * 32));

    for (int mt = 0; mt < Mv; mt += MT) {
        __syncthreads();
        {
            float4* gd = (float4*)g_s;
            const float4* gs = g_glob + (size_t)mt * 8;
            for (int i = tid; i < MT * 8; i += 128) gd[i] = gs[i];
        }
        __syncthreads();
        const ulonglong2* gu = (const ulonglong2*)g_s;

#pragma unroll 2
        for (int mm = 0; mm < MT; mm++) {
            int m = mt + mm;
            ulonglong2 p0 = phi_u[m * 2 + 0];
            ulonglong2 p1 = phi_u[m * 2 + 1];

            ULL sa = f2_mul(tA0, p0.x);
            sa = f2_fma(tA1, p0.y, sa);
            sa = f2_fma(tA2, p1.x, sa);
            sa = f2_fma(tA3, p1.y, sa);
            ULL sb = f2_mul(tB0, p0.x);
            sb = f2_fma(tB1, p0.y, sb);
            sb = f2_fma(tB2, p1.x, sb);
            sb = f2_fma(tB3, p1.y, sb);

            float2 fa = f2_unpack(sa);
            float2 fb = f2_unpack(sb);
            float pw0 = ex2(fa.x + fa.y);   // theta pre-scaled by 1/ln2
            float pw1 = ex2(fb.x + fb.y);
            lsum0 += pw0;
            lsum1 += pw1;
            ULL pp0 = f2_pack(pw0, pw0);
            ULL pp1 = f2_pack(pw1, pw1);

            const ulonglong2* gm = gu + (size_t)mm * 8;
#pragma unroll
            for (int jj = 0; jj < 8; jj++) {
                ulonglong2 gv = gm[jj];
                acc0[jj * 2 + 0] = f2_fma(pp0, gv.x, acc0[jj * 2 + 0]);
                acc0[jj * 2 + 1] = f2_fma(pp0, gv.y, acc0[jj * 2 + 1]);
                acc1[jj * 2 + 0] = f2_fma(pp1, gv.x, acc1[jj * 2 + 0]);
                acc1[jj * 2 + 1] = f2_fma(pp1, gv.y, acc1[jj * 2 + 1]);
            }
        }
    }

    // epilogue: out[co] = x[co] + sigma/lsum * sum_j Wattn[co][j]*acc[j]
    float sgm = sigma[0];
    float sg0 = sgm / lsum0;
    float sg1 = sgm / lsum1;
    const float* xp0 = x + ((size_t)b * Cv) * Nv + n0;
    const float* xp1 = x + ((size_t)b * Cv) * Nv + n1;
    float* op0 = out + ((size_t)b * Cv) * Nv + n0;
    float* op1 = out + ((size_t)b * Cv) * Nv + n1;
    const ulonglong2* wa_u = (const ulonglong2*)wa_s;

#pragma unroll 4
    for (int co = 0; co < 64; co++) {
        const ulonglong2* wr = wa_u + (size_t)co * 8;
        ULL d0 = 0ULL, d1 = 0ULL;
#pragma unroll
        for (int jj = 0; jj < 8; jj++) {
            ulonglong2 wv = wr[jj];
            d0 = f2_fma(acc0[jj * 2 + 0], wv.x, d0);
            d0 = f2_fma(acc0[jj * 2 + 1], wv.y, d0);
            d1 = f2_fma(acc1[jj * 2 + 0], wv.x, d1);
            d1 = f2_fma(acc1[jj * 2 + 1], wv.y, d1);
        }
        float2 e0 = f2_unpack(d0);
        float2 e1 = f2_unpack(d1);
        op0[(size_t)co * Nv] = xp0[(size_t)co * Nv] + sg0 * (e0.x + e0.y);
        op1[(size_t)co * Nv] = xp1[(size_t)co * Nv] + sg1 * (e1.x + e1.y);
    }
}

// ======================================================================
// launch
// ======================================================================
extern "C" void kernel_launch(void* const* d_in, const int* in_sizes, int n_in,
                              void* d_out, int out_size) {
    const float* x     = (const float*)d_in[0];
    const float* Wth   = (const float*)d_in[1];
    const float* Wphi  = (const float*)d_in[2];
    const float* Wg    = (const float*)d_in[3];
    const float* Wattn = (const float*)d_in[4];
    const float* sigma = (const float*)d_in[5];
    float* out = (float*)d_out;

    cudaFuncSetAttribute(attn_kernel,
                         cudaFuncAttributeMaxDynamicSharedMemorySize, 73728);

    prep_kernel<<<dim3(24, Bv), 256>>>(x, Wth, Wphi, Wg);
    attn_kernel<<<dim3(16, Bv), 128, 73728>>>(x, Wattn, sigma, out);
}

// round 5
// speedup vs baseline: 2.7377x; 2.4324x over previous
#include <cuda_runtime.h>
#include <cuda_bf16.h>

// ---------------- problem constants ----------------
#define Bv 16
#define Cv 64
#define Nv 4096
#define Mv 1024
#define LN2R 1.4426950408889634f

typedef unsigned long long ULL;

// ---------------- helpers ----------------
__device__ __forceinline__ ULL f2_fma(ULL a, ULL b, ULL c) {
    ULL d; asm("fma.rn.f32x2 %0, %1, %2, %3;" : "=l"(d) : "l"(a), "l"(b), "l"(c)); return d;
}
__device__ __forceinline__ ULL f2_pack(float lo, float hi) {
    ULL r;
    asm("mov.b64 %0, {%1, %2};" : "=l"(r)
        : "r"(__float_as_uint(lo)), "r"(__float_as_uint(hi)));
    return r;
}
__device__ __forceinline__ float2 f2_unpack(ULL v) {
    unsigned lo, hi;
    asm("mov.b64 {%0, %1}, %2;" : "=r"(lo), "=r"(hi) : "l"(v));
    return make_float2(__uint_as_float(lo), __uint_as_float(hi));
}
__device__ __forceinline__ float ex2f(float x) {
    float r; asm("ex2.approx.f32 %0, %1;" : "=f"(r) : "f"(x)); return r;
}
__device__ __forceinline__ float tf32r(float x) {
    float r; asm("cvt.rna.tf32.f32 %0, %1;" : "=f"(r) : "f"(x)); return r;
}
// pack (lo, hi) floats -> bf16x2 (hi in upper 16 bits)
__device__ __forceinline__ unsigned pack_bf16x2(float lo, float hi) {
    unsigned r;
    asm("cvt.rn.bf16x2.f32 %0, %1, %2;" : "=r"(r) : "f"(hi), "f"(lo));
    return r;
}

// mma.sync m16n8k8 tf32: D = A(16x8) * B(8x8) + C
__device__ __forceinline__ void mma_qk(float d[4], const unsigned a[4],
                                       unsigned b0, unsigned b1,
                                       float c0, float c1, float c2, float c3) {
    asm("mma.sync.aligned.m16n8k8.row.col.f32.tf32.tf32.f32 "
        "{%0,%1,%2,%3},{%4,%5,%6,%7},{%8,%9},{%10,%11,%12,%13};"
        : "=f"(d[0]), "=f"(d[1]), "=f"(d[2]), "=f"(d[3])
        : "r"(a[0]), "r"(a[1]), "r"(a[2]), "r"(a[3]),
          "r"(b0), "r"(b1), "f"(c0), "f"(c1), "f"(c2), "f"(c3));
}
// mma.sync m16n8k16 bf16: D = A(16x16) * B(16x8) + C (accumulate in place)
__device__ __forceinline__ void mma_pv(float d[4], const unsigned a[4],
                                       unsigned b0, unsigned b1) {
    asm("mma.sync.aligned.m16n8k16.row.col.f32.bf16.bf16.f32 "
        "{%0,%1,%2,%3},{%4,%5,%6,%7},{%8,%9},{%0,%1,%2,%3};"
        : "+f"(d[0]), "+f"(d[1]), "+f"(d[2]), "+f"(d[3])
        : "r"(a[0]), "r"(a[1]), "r"(a[2]), "r"(a[3]), "r"(b0), "r"(b1));
}

// ---------------- scratch ----------------
__device__ float d_theta[Bv * Nv * 8];            // [b][n][k] tf32-rounded, *LN2R
__device__ float d_phi  [Bv * Mv * 8];            // [b][m][pairs (p,p+4)] tf32-rounded
__device__ __nv_bfloat16 d_gTb[Bv * 32 * Mv];     // [b][j][m] bf16

// ======================================================================
// prep_kernel: theta (blocks 0..15) + phi/gT (blocks 16..23). 256 thr.
// ======================================================================
__global__ void __launch_bounds__(256)
prep_kernel(const float* __restrict__ x,
            const float* __restrict__ Wth,
            const float* __restrict__ Wphi,
            const float* __restrict__ Wg) {
    __shared__ float sm[512 + 2048 + 128 * 41];
    int tid = threadIdx.x;
    int b = blockIdx.y;

    if (blockIdx.x < 16) {
        float* Ws = sm;
        for (int i = tid; i < 512; i += 256) Ws[i] = Wth[i];
        __syncthreads();
        int n = blockIdx.x * 256 + tid;
        const float* xp = x + ((size_t)b * Cv) * Nv + n;
        float acc[8];
#pragma unroll
        for (int k = 0; k < 8; k++) acc[k] = 0.f;
#pragma unroll
        for (int cc = 0; cc < 64; cc += 16) {
            float xv[16];
#pragma unroll
            for (int u = 0; u < 16; u++) xv[u] = xp[(size_t)(cc + u) * Nv];
#pragma unroll
            for (int u = 0; u < 16; u++)
#pragma unroll
                for (int k = 0; k < 8; k++)
                    acc[k] = fmaf(Ws[k * 64 + cc + u], xv[u], acc[k]);
        }
        float* dst = d_theta + ((size_t)(b * Nv + n)) * 8;
        ((float4*)dst)[0] = make_float4(tf32r(acc[0] * LN2R), tf32r(acc[1] * LN2R),
                                        tf32r(acc[2] * LN2R), tf32r(acc[3] * LN2R));
        ((float4*)dst)[1] = make_float4(tf32r(acc[4] * LN2R), tf32r(acc[5] * LN2R),
                                        tf32r(acc[6] * LN2R), tf32r(acc[7] * LN2R));
    } else {
        float* Wpt = sm;
        float* Wgt = sm + 512;
        float* red = sm + 2560;
        for (int i = tid; i < 512; i += 256) {
            int k = i >> 6, c = i & 63;
            Wpt[c * 8 + k] = Wphi[i];
        }
        for (int i = tid; i < 2048; i += 256) {
            int j = i >> 6, c = i & 63;
            Wgt[c * 32 + j] = Wg[i];
        }
        __syncthreads();

        int lm = tid & 127, half = tid >> 7;
        int m = (blockIdx.x - 16) * 128 + lm;
        int h2 = m >> 5, w2 = m & 31;
        int n0 = ((h2 << 1) + half) * 64 + (w2 << 1);
        const float* xb = x + ((size_t)b * Cv) * Nv;

        float bp[8], bg[32];
#pragma unroll
        for (int k = 0; k < 8; k++) bp[k] = -3.4e38f;
#pragma unroll
        for (int j = 0; j < 32; j++) bg[j] = -3.4e38f;

#pragma unroll 1
        for (int p = 0; p < 2; p++) {
            const float* xp = xb + n0 + p;
            float ap[8], ag[32];
#pragma unroll
            for (int k = 0; k < 8; k++) ap[k] = 0.f;
#pragma unroll
            for (int j = 0; j < 32; j++) ag[j] = 0.f;
#pragma unroll 8
            for (int c = 0; c < 64; c++) {
                float xv = xp[(size_t)c * Nv];
                const float4* wp = (const float4*)&Wpt[c * 8];
                float4 w0 = wp[0], w1 = wp[1];
                ap[0] = fmaf(w0.x, xv, ap[0]); ap[1] = fmaf(w0.y, xv, ap[1]);
                ap[2] = fmaf(w0.z, xv, ap[2]); ap[3] = fmaf(w0.w, xv, ap[3]);
                ap[4] = fmaf(w1.x, xv, ap[4]); ap[5] = fmaf(w1.y, xv, ap[5]);
                ap[6] = fmaf(w1.z, xv, ap[6]); ap[7] = fmaf(w1.w, xv, ap[7]);
                const float4* wg = (const float4*)&Wgt[c * 32];
#pragma unroll
                for (int q = 0; q < 8; q++) {
                    float4 wv = wg[q];
                    ag[q * 4 + 0] = fmaf(wv.x, xv, ag[q * 4 + 0]);
                    ag[q * 4 + 1] = fmaf(wv.y, xv, ag[q * 4 + 1]);
                    ag[q * 4 + 2] = fmaf(wv.z, xv, ag[q * 4 + 2]);
                    ag[q * 4 + 3] = fmaf(wv.w, xv, ag[q * 4 + 3]);
                }
            }
#pragma unroll
            for (int k = 0; k < 8; k++) bp[k] = fmaxf(bp[k], ap[k]);
#pragma unroll
            for (int j = 0; j < 32; j++) bg[j] = fmaxf(bg[j], ag[j]);
        }

        if (half) {
            float* r = red + lm * 41;
#pragma unroll
            for (int k = 0; k < 8; k++) r[k] = bp[k];
#pragma unroll
            for (int j = 0; j < 32; j++) r[8 + j] = bg[j];
        }
        __syncthreads();
        if (!half) {
            const float* r = red + lm * 41;
#pragma unroll
            for (int k = 0; k < 8; k++) bp[k] = fmaxf(bp[k], r[k]);
#pragma unroll
            for (int j = 0; j < 32; j++) bg[j] = fmaxf(bg[j], r[8 + j]);

            // phi: tf32-rounded, interleaved pairs (p, p+4)
            float* pd = d_phi + ((size_t)(b * Mv + m)) * 8;
            ((float4*)pd)[0] = make_float4(tf32r(bp[0]), tf32r(bp[4]),
                                           tf32r(bp[1]), tf32r(bp[5]));
            ((float4*)pd)[1] = make_float4(tf32r(bp[2]), tf32r(bp[6]),
                                           tf32r(bp[3]), tf32r(bp[7]));
            // g transposed bf16 [j][m]
#pragma unroll
            for (int j = 0; j < 32; j++)
                d_gTb[((size_t)(b * 32 + j)) * Mv + m] = __float2bfloat16(bg[j]);
        }
    }
}

// ======================================================================
// attn_kernel: mma.sync FA2-style. 128 thr = 4 warps x 32q. grid (32, B).
// ======================================================================
#define GT_PITCH 136   // bf16 elements per row (272B, conflict-free B-frag loads)

__global__ void __launch_bounds__(128)
attn_kernel(const float* __restrict__ x,
            const float* __restrict__ Wattn,
            const float* __restrict__ sigma,
            float* __restrict__ out) {
    __shared__ float phi_s[128 * 8];                 // 4KB  [m][pair*2]
    __shared__ __nv_bfloat16 gt_s[32 * GT_PITCH];    // 8.5KB [j][m] padded
    __shared__ float o_s[128 * 32];                  // 16KB
    __shared__ float wa_s[2048];                     // 8KB
    __shared__ float lsum_s[128];

    int tid = threadIdx.x;
    int w = tid >> 5, l = tid & 31;
    int g = l >> 2, k4 = l & 3;
    int b = blockIdx.y;
    int qbase = blockIdx.x * 128;

    // theta A-frags (tf32), 2 q-tiles of 16, loaded once from gmem
    unsigned a[2][4];
#pragma unroll
    for (int t = 0; t < 2; t++) {
        const float* th = d_theta + ((size_t)(b * Nv + qbase + w * 32 + t * 16)) * 8;
        a[t][0] = __float_as_uint(th[g * 8 + k4]);
        a[t][1] = __float_as_uint(th[(g + 8) * 8 + k4]);
        a[t][2] = __float_as_uint(th[g * 8 + k4 + 4]);
        a[t][3] = __float_as_uint(th[(g + 8) * 8 + k4 + 4]);
    }

    float o[2][4][4];
#pragma unroll
    for (int t = 0; t < 2; t++)
#pragma unroll
        for (int jt = 0; jt < 4; jt++)
#pragma unroll
            for (int i = 0; i < 4; i++) o[t][jt][i] = 0.f;
    float lsum[2][2] = {{0.f, 0.f}, {0.f, 0.f}};

    for (int mt = 0; mt < 8; mt++) {
        __syncthreads();
        // stage phi tile [128m x 32B]
        {
            const float4* src = (const float4*)(d_phi + ((size_t)(b * Mv + mt * 128)) * 8);
            float4* dst = (float4*)phi_s;
            for (int i = tid; i < 256; i += 128) dst[i] = src[i];
        }
        // stage gT tile [32j x 128m] bf16 into padded rows
        {
            for (int i = tid; i < 512; i += 128) {
                int row = i >> 4, c = i & 15;
                const uint4* src = (const uint4*)(d_gTb +
                    ((size_t)(b * 32 + row)) * Mv + mt * 128 + c * 8);
                *(uint4*)&gt_s[row * GT_PITCH + c * 8] = *src;
            }
        }
        __syncthreads();

#pragma unroll 2
        for (int ms = 0; ms < 8; ms++) {
            int m0 = ms * 16;
            // phi B-frags for two m8 halves
            float2 bb0 = *(const float2*)&phi_s[(m0 + g) * 8 + k4 * 2];
            float2 bb1 = *(const float2*)&phi_s[(m0 + 8 + g) * 8 + k4 * 2];

            // QK: S[qt][h][4]
            float s[2][2][4];
#pragma unroll
            for (int t = 0; t < 2; t++) {
                mma_qk(s[t][0], a[t], __float_as_uint(bb0.x), __float_as_uint(bb0.y),
                       0.f, 0.f, 0.f, 0.f);
                mma_qk(s[t][1], a[t], __float_as_uint(bb1.x), __float_as_uint(bb1.y),
                       0.f, 0.f, 0.f, 0.f);
            }

            // softmax numerators + row-sum partials + pack to bf16 A-frags
            // m16n8k16 A-frag: pa[0]=A[g][2k4,2k4+1] pa[1]=A[g+8][..]
            //                  pa[2]=A[g][2k4+8,+9]  pa[3]=A[g+8][2k4+8,+9]
            // h selects the m8 half -> col offset h*8 -> index h*2 + {0,1}
            unsigned pa[2][4];
#pragma unroll
            for (int t = 0; t < 2; t++) {
#pragma unroll
                for (int h = 0; h < 2; h++) {
                    float e0 = ex2f(s[t][h][0]);
                    float e1 = ex2f(s[t][h][1]);
                    float e2 = ex2f(s[t][h][2]);
                    float e3 = ex2f(s[t][h][3]);
                    lsum[t][0] += e0 + e1;
                    lsum[t][1] += e2 + e3;
                    pa[t][h * 2 + 0] = pack_bf16x2(e0, e1);  // rows g
                    pa[t][h * 2 + 1] = pack_bf16x2(e2, e3);  // rows g+8
                }
            }

            // PV: O[qt][jt] += P * G
#pragma unroll
            for (int jt = 0; jt < 4; jt++) {
                const __nv_bfloat16* gr = &gt_s[(jt * 8 + g) * GT_PITCH + m0];
                unsigned b0 = *(const unsigned*)(gr + 2 * k4);
                unsigned b1 = *(const unsigned*)(gr + 2 * k4 + 8);
#pragma unroll
                for (int t = 0; t < 2; t++) mma_pv(o[t][jt], pa[t], b0, b1);
            }
        }
    }

    // row-sum reduce across lane quads (cols of S live on l%4 lanes)
#pragma unroll
    for (int t = 0; t < 2; t++)
#pragma unroll
        for (int r = 0; r < 2; r++) {
            float v = lsum[t][r];
            v += __shfl_xor_sync(0xFFFFFFFF, v, 1);
            v += __shfl_xor_sync(0xFFFFFFFF, v, 2);
            lsum[t][r] = v;
        }
    if (k4 == 0) {
#pragma unroll
        for (int t = 0; t < 2; t++) {
            lsum_s[w * 32 + t * 16 + g] = lsum[t][0];
            lsum_s[w * 32 + t * 16 + g + 8] = lsum[t][1];
        }
    }

    // store O frags to smem
#pragma unroll
    for (int t = 0; t < 2; t++) {
        int q0 = w * 32 + t * 16;
#pragma unroll
        for (int jt = 0; jt < 4; jt++) {
            int jc = jt * 8 + 2 * k4;
            *(float2*)&o_s[(q0 + g) * 32 + jc] = make_float2(o[t][jt][0], o[t][jt][1]);
            *(float2*)&o_s[(q0 + g + 8) * 32 + jc] = make_float2(o[t][jt][2], o[t][jt][3]);
        }
    }
    // stage W_attn
    for (int i = tid; i < 2048; i += 128) wa_s[i] = Wattn[i];
    __syncthreads();

    // epilogue: thread <-> query
    float av[32];
    {
        const float4* os = (const float4*)&o_s[tid * 32];
        float inv = sigma[0] / lsum_s[tid];
#pragma unroll
        for (int i = 0; i < 8; i++) {
            float4 v = os[i];
            av[i * 4 + 0] = v.x * inv; av[i * 4 + 1] = v.y * inv;
            av[i * 4 + 2] = v.z * inv; av[i * 4 + 3] = v.w * inv;
        }
    }
    ULL acc[16];
#pragma unroll
    for (int i = 0; i < 16; i++) acc[i] = f2_pack(av[2 * i], av[2 * i + 1]);

    int n = qbase + tid;
    const float* xp = x + ((size_t)b * Cv) * Nv + n;
    float* op = out + ((size_t)b * Cv) * Nv + n;
    const ulonglong2* wa_u = (const ulonglong2*)wa_s;
#pragma unroll 4
    for (int co = 0; co < 64; co++) {
        const ulonglong2* wr = wa_u + (size_t)co * 8;
        ULL d2 = 0ULL;
#pragma unroll
        for (int jj = 0; jj < 8; jj++) {
            ulonglong2 wv = wr[jj];
            d2 = f2_fma(acc[jj * 2 + 0], wv.x, d2);
            d2 = f2_fma(acc[jj * 2 + 1], wv.y, d2);
        }
        float2 df = f2_unpack(d2);
        op[(size_t)co * Nv] = xp[(size_t)co * Nv] + (df.x + df.y);
    }
}

// ======================================================================
// launch
// ======================================================================
extern "C" void kernel_launch(void* const* d_in, const int* in_sizes, int n_in,
                              void* d_out, int out_size) {
    const float* x     = (const float*)d_in[0];
    const float* Wth   = (const float*)d_in[1];
    const float* Wphi  = (const float*)d_in[2];
    const float* Wg    = (const float*)d_in[3];
    const float* Wattn = (const float*)d_in[4];
    const float* sigma = (const float*)d_in[5];
    float* out = (float*)d_out;

    prep_kernel<<<dim3(24, Bv), 256>>>(x, Wth, Wphi, Wg);
    attn_kernel<<<dim3(Nv / 128, Bv), 128>>>(x, Wattn, sigma, out);
}

// round 6
// speedup vs baseline: 2.8186x; 1.0295x over previous
#include <cuda_runtime.h>
#include <cuda_bf16.h>

// ---------------- problem constants ----------------
#define Bv 16
#define Cv 64
#define Nv 4096
#define Mv 1024
#define LN2R 1.4426950408889634f

typedef unsigned long long ULL;

// ---------------- helpers ----------------
__device__ __forceinline__ ULL f2_fma(ULL a, ULL b, ULL c) {
    ULL d; asm("fma.rn.f32x2 %0, %1, %2, %3;" : "=l"(d) : "l"(a), "l"(b), "l"(c)); return d;
}
__device__ __forceinline__ ULL f2_pack(float lo, float hi) {
    ULL r;
    asm("mov.b64 %0, {%1, %2};" : "=l"(r)
        : "r"(__float_as_uint(lo)), "r"(__float_as_uint(hi)));
    return r;
}
__device__ __forceinline__ float2 f2_unpack(ULL v) {
    unsigned lo, hi;
    asm("mov.b64 {%0, %1}, %2;" : "=r"(lo), "=r"(hi) : "l"(v));
    return make_float2(__uint_as_float(lo), __uint_as_float(hi));
}
__device__ __forceinline__ float ex2f(float x) {
    float r; asm("ex2.approx.f32 %0, %1;" : "=f"(r) : "f"(x)); return r;
}
__device__ __forceinline__ float tf32r(float x) {
    float r; asm("cvt.rna.tf32.f32 %0, %1;" : "=f"(r) : "f"(x)); return r;
}
__device__ __forceinline__ unsigned pack_bf16x2(float lo, float hi) {
    unsigned r;
    asm("cvt.rn.bf16x2.f32 %0, %1, %2;" : "=r"(r) : "f"(hi), "f"(lo));
    return r;
}
__device__ __forceinline__ unsigned smem_u32(const void* p) {
    unsigned a;
    asm("{.reg .u64 t; cvta.to.shared.u64 t, %1; cvt.u32.u64 %0, t;}"
        : "=r"(a) : "l"(p));
    return a;
}
__device__ __forceinline__ void cpa16(unsigned dst, const void* src) {
    asm volatile("cp.async.cg.shared.global [%0], [%1], 16;"
                 :: "r"(dst), "l"(src));
}
#define CPA_COMMIT() asm volatile("cp.async.commit_group;" ::: "memory")
#define CPA_WAIT0()  asm volatile("cp.async.wait_group 0;" ::: "memory")

// mma.sync m16n8k8 tf32
__device__ __forceinline__ void mma_qk(float d[4], const unsigned a[4],
                                       unsigned b0, unsigned b1) {
    asm("mma.sync.aligned.m16n8k8.row.col.f32.tf32.tf32.f32 "
        "{%0,%1,%2,%3},{%4,%5,%6,%7},{%8,%9},{%10,%11,%12,%13};"
        : "=f"(d[0]), "=f"(d[1]), "=f"(d[2]), "=f"(d[3])
        : "r"(a[0]), "r"(a[1]), "r"(a[2]), "r"(a[3]),
          "r"(b0), "r"(b1), "f"(0.f), "f"(0.f), "f"(0.f), "f"(0.f));
}
// mma.sync m16n8k16 bf16 (accumulate in place)
__device__ __forceinline__ void mma_pv(float d[4], const unsigned a[4],
                                       unsigned b0, unsigned b1) {
    asm("mma.sync.aligned.m16n8k16.row.col.f32.bf16.bf16.f32 "
        "{%0,%1,%2,%3},{%4,%5,%6,%7},{%8,%9},{%0,%1,%2,%3};"
        : "+f"(d[0]), "+f"(d[1]), "+f"(d[2]), "+f"(d[3])
        : "r"(a[0]), "r"(a[1]), "r"(a[2]), "r"(a[3]), "r"(b0), "r"(b1));
}

// ---------------- scratch ----------------
__device__ float d_theta[Bv * Nv * 8];            // [b][n][k] tf32-rounded, *LN2R
__device__ float d_phi  [Bv * Mv * 8];            // [b][m][pairs (p,p+4)] tf32-rounded
__device__ __nv_bfloat16 d_gTb[Bv * 32 * Mv];     // [b][j][m] bf16

// ======================================================================
// prep_kernel: theta (blocks 0..15) + phi/gT (blocks 16..23). 256 thr.
// ======================================================================
__global__ void __launch_bounds__(256)
prep_kernel(const float* __restrict__ x,
            const float* __restrict__ Wth,
            const float* __restrict__ Wphi,
            const float* __restrict__ Wg) {
    __shared__ float sm[512 + 2048 + 128 * 41];
    int tid = threadIdx.x;
    int b = blockIdx.y;

    if (blockIdx.x < 16) {
        float* Ws = sm;
        for (int i = tid; i < 512; i += 256) Ws[i] = Wth[i];
        __syncthreads();
        int n = blockIdx.x * 256 + tid;
        const float* xp = x + ((size_t)b * Cv) * Nv + n;
        float acc[8];
#pragma unroll
        for (int k = 0; k < 8; k++) acc[k] = 0.f;
#pragma unroll
        for (int cc = 0; cc < 64; cc += 16) {
            float xv[16];
#pragma unroll
            for (int u = 0; u < 16; u++) xv[u] = xp[(size_t)(cc + u) * Nv];
#pragma unroll
            for (int u = 0; u < 16; u++)
#pragma unroll
                for (int k = 0; k < 8; k++)
                    acc[k] = fmaf(Ws[k * 64 + cc + u], xv[u], acc[k]);
        }
        float* dst = d_theta + ((size_t)(b * Nv + n)) * 8;
        ((float4*)dst)[0] = make_float4(tf32r(acc[0] * LN2R), tf32r(acc[1] * LN2R),
                                        tf32r(acc[2] * LN2R), tf32r(acc[3] * LN2R));
        ((float4*)dst)[1] = make_float4(tf32r(acc[4] * LN2R), tf32r(acc[5] * LN2R),
                                        tf32r(acc[6] * LN2R), tf32r(acc[7] * LN2R));
    } else {
        float* Wpt = sm;
        float* Wgt = sm + 512;
        float* red = sm + 2560;
        for (int i = tid; i < 512; i += 256) {
            int k = i >> 6, c = i & 63;
            Wpt[c * 8 + k] = Wphi[i];
        }
        for (int i = tid; i < 2048; i += 256) {
            int j = i >> 6, c = i & 63;
            Wgt[c * 32 + j] = Wg[i];
        }
        __syncthreads();

        int lm = tid & 127, half = tid >> 7;
        int m = (blockIdx.x - 16) * 128 + lm;
        int h2 = m >> 5, w2 = m & 31;
        int n0 = ((h2 << 1) + half) * 64 + (w2 << 1);
        const float* xb = x + ((size_t)b * Cv) * Nv;

        float bp[8], bg[32];
#pragma unroll
        for (int k = 0; k < 8; k++) bp[k] = -3.4e38f;
#pragma unroll
        for (int j = 0; j < 32; j++) bg[j] = -3.4e38f;

#pragma unroll 1
        for (int p = 0; p < 2; p++) {
            const float* xp = xb + n0 + p;
            float ap[8], ag[32];
#pragma unroll
            for (int k = 0; k < 8; k++) ap[k] = 0.f;
#pragma unroll
            for (int j = 0; j < 32; j++) ag[j] = 0.f;
#pragma unroll 8
            for (int c = 0; c < 64; c++) {
                float xv = xp[(size_t)c * Nv];
                const float4* wp = (const float4*)&Wpt[c * 8];
                float4 w0 = wp[0], w1 = wp[1];
                ap[0] = fmaf(w0.x, xv, ap[0]); ap[1] = fmaf(w0.y, xv, ap[1]);
                ap[2] = fmaf(w0.z, xv, ap[2]); ap[3] = fmaf(w0.w, xv, ap[3]);
                ap[4] = fmaf(w1.x, xv, ap[4]); ap[5] = fmaf(w1.y, xv, ap[5]);
                ap[6] = fmaf(w1.z, xv, ap[6]); ap[7] = fmaf(w1.w, xv, ap[7]);
                const float4* wg = (const float4*)&Wgt[c * 32];
#pragma unroll
                for (int q = 0; q < 8; q++) {
                    float4 wv = wg[q];
                    ag[q * 4 + 0] = fmaf(wv.x, xv, ag[q * 4 + 0]);
                    ag[q * 4 + 1] = fmaf(wv.y, xv, ag[q * 4 + 1]);
                    ag[q * 4 + 2] = fmaf(wv.z, xv, ag[q * 4 + 2]);
                    ag[q * 4 + 3] = fmaf(wv.w, xv, ag[q * 4 + 3]);
                }
            }
#pragma unroll
            for (int k = 0; k < 8; k++) bp[k] = fmaxf(bp[k], ap[k]);
#pragma unroll
            for (int j = 0; j < 32; j++) bg[j] = fmaxf(bg[j], ag[j]);
        }

        if (half) {
            float* r = red + lm * 41;
#pragma unroll
            for (int k = 0; k < 8; k++) r[k] = bp[k];
#pragma unroll
            for (int j = 0; j < 32; j++) r[8 + j] = bg[j];
        }
        __syncthreads();
        if (!half) {
            const float* r = red + lm * 41;
#pragma unroll
            for (int k = 0; k < 8; k++) bp[k] = fmaxf(bp[k], r[k]);
#pragma unroll
            for (int j = 0; j < 32; j++) bg[j] = fmaxf(bg[j], r[8 + j]);

            float* pd = d_phi + ((size_t)(b * Mv + m)) * 8;
            ((float4*)pd)[0] = make_float4(tf32r(bp[0]), tf32r(bp[4]),
                                           tf32r(bp[1]), tf32r(bp[5]));
            ((float4*)pd)[1] = make_float4(tf32r(bp[2]), tf32r(bp[6]),
                                           tf32r(bp[3]), tf32r(bp[7]));
#pragma unroll
            for (int j = 0; j < 32; j++)
                d_gTb[((size_t)(b * 32 + j)) * Mv + m] = __float2bfloat16(bg[j]);
        }
    }
}

// ======================================================================
// attn_kernel: 256 thr = 8 warps x 16q = 128 q/CTA. grid (32, B).
// cp.async double-buffered staging; epilogue arrays overlay staging smem.
// smem layout (25600B):
//   [0:8192)       phi double buffer (2 x 4KB)     | overlay: o_s [0:16384)
//   [8192:25600)   gt double buffer (2 x 8704B)    | overlay: wa_s [16384:24576)
//                                                  |          lsum [24576:25088)
// ======================================================================
#define GT_PITCH 136   // bf16 per row (272B)

__global__ void __launch_bounds__(256)
attn_kernel(const float* __restrict__ x,
            const float* __restrict__ Wattn,
            const float* __restrict__ sigma,
            float* __restrict__ out) {
    __shared__ __align__(16) char smraw[25600];
    unsigned sbase = smem_u32(smraw);

    int tid = threadIdx.x;
    int w = tid >> 5, l = tid & 31;
    int g = l >> 2, k4 = l & 3;
    int b = blockIdx.y;
    int qbase = blockIdx.x * 128;

    // theta A-frag: 16 queries per warp
    unsigned a[4];
    {
        const float* th = d_theta + ((size_t)(b * Nv + qbase + w * 16)) * 8;
        a[0] = __float_as_uint(th[g * 8 + k4]);
        a[1] = __float_as_uint(th[(g + 8) * 8 + k4]);
        a[2] = __float_as_uint(th[g * 8 + k4 + 4]);
        a[3] = __float_as_uint(th[(g + 8) * 8 + k4 + 4]);
    }

    float o[4][4];
#pragma unroll
    for (int jt = 0; jt < 4; jt++)
#pragma unroll
        for (int i = 0; i < 4; i++) o[jt][i] = 0.f;
    float lsum0 = 0.f, lsum1 = 0.f;

    const char* phi_g = (const char*)(d_phi + (size_t)b * (Mv * 8));
    const char* gt_g = (const char*)(d_gTb + (size_t)b * (32 * Mv));

    // ---- stage tile 0 into buffer 0 ----
    {
        unsigned pdst = sbase + tid * 16;
        cpa16(pdst, phi_g + tid * 16);
        int row0 = tid >> 4, c0 = tid & 15;
        cpa16(sbase + 8192 + row0 * 272 + c0 * 16,
              gt_g + (size_t)row0 * (Mv * 2) + c0 * 16);
        int i2 = tid + 256;
        int row1 = i2 >> 4, c1 = i2 & 15;
        cpa16(sbase + 8192 + row1 * 272 + c1 * 16,
              gt_g + (size_t)row1 * (Mv * 2) + c1 * 16);
        CPA_COMMIT();
    }

#pragma unroll 1
    for (int mt = 0; mt < 8; mt++) {
        CPA_WAIT0();
        __syncthreads();

        int buf = mt & 1;
        // prefetch next tile into other buffer
        if (mt < 7) {
            int nb = buf ^ 1;
            unsigned pbase = sbase + nb * 4096;
            unsigned gbase = sbase + 8192 + nb * 8704;
            const char* psrc = phi_g + (size_t)(mt + 1) * 4096;
            const char* gsrc = gt_g + (size_t)(mt + 1) * 256;
            cpa16(pbase + tid * 16, psrc + tid * 16);
            int row0 = tid >> 4, c0 = tid & 15;
            cpa16(gbase + row0 * 272 + c0 * 16,
                  gsrc + (size_t)row0 * (Mv * 2) + c0 * 16);
            int i2 = tid + 256;
            int row1 = i2 >> 4, c1 = i2 & 15;
            cpa16(gbase + row1 * 272 + c1 * 16,
                  gsrc + (size_t)row1 * (Mv * 2) + c1 * 16);
            CPA_COMMIT();
        }

        const float* phi_b = (const float*)(smraw + buf * 4096);
        const __nv_bfloat16* gt_b =
            (const __nv_bfloat16*)(smraw + 8192 + buf * 8704);

#pragma unroll 2
        for (int ms = 0; ms < 8; ms++) {
            int m0 = ms * 16;
            float2 bb0 = *(const float2*)&phi_b[(m0 + g) * 8 + k4 * 2];
            float2 bb1 = *(const float2*)&phi_b[(m0 + 8 + g) * 8 + k4 * 2];

            float s0[4], s1[4];
            mma_qk(s0, a, __float_as_uint(bb0.x), __float_as_uint(bb0.y));
            mma_qk(s1, a, __float_as_uint(bb1.x), __float_as_uint(bb1.y));

            // P = ex2(S); m16n8k16 A-frag: [h*2+0]=rows g, [h*2+1]=rows g+8
            unsigned pa[4];
            {
                float e0 = ex2f(s0[0]), e1 = ex2f(s0[1]);
                float e2 = ex2f(s0[2]), e3 = ex2f(s0[3]);
                lsum0 += e0 + e1; lsum1 += e2 + e3;
                pa[0] = pack_bf16x2(e0, e1);
                pa[1] = pack_bf16x2(e2, e3);
                float f0 = ex2f(s1[0]), f1 = ex2f(s1[1]);
                float f2 = ex2f(s1[2]), f3 = ex2f(s1[3]);
                lsum0 += f0 + f1; lsum1 += f2 + f3;
                pa[2] = pack_bf16x2(f0, f1);
                pa[3] = pack_bf16x2(f2, f3);
            }

#pragma unroll
            for (int jt = 0; jt < 4; jt++) {
                const __nv_bfloat16* gr = &gt_b[(jt * 8 + g) * GT_PITCH + m0];
                unsigned b0 = *(const unsigned*)(gr + 2 * k4);
                unsigned b1 = *(const unsigned*)(gr + 2 * k4 + 8);
                mma_pv(o[jt], pa, b0, b1);
            }
        }
    }

    // quad-reduce row sums (cols live on l%4)
    {
        lsum0 += __shfl_xor_sync(0xFFFFFFFF, lsum0, 1);
        lsum0 += __shfl_xor_sync(0xFFFFFFFF, lsum0, 2);
        lsum1 += __shfl_xor_sync(0xFFFFFFFF, lsum1, 1);
        lsum1 += __shfl_xor_sync(0xFFFFFFFF, lsum1, 2);
    }

    __syncthreads();   // all tile compute done; safe to overlay epilogue arrays
    float* o_s = (float*)smraw;                 // [128][32]
    float* wa_s = (float*)(smraw + 16384);      // [2048]
    float* lsum_s = (float*)(smraw + 24576);    // [128]

    if (k4 == 0) {
        lsum_s[w * 16 + g] = lsum0;
        lsum_s[w * 16 + g + 8] = lsum1;
    }
    {
        int q0 = w * 16;
#pragma unroll
        for (int jt = 0; jt < 4; jt++) {
            int jc = jt * 8 + 2 * k4;
            *(float2*)&o_s[(q0 + g) * 32 + jc] = make_float2(o[jt][0], o[jt][1]);
            *(float2*)&o_s[(q0 + g + 8) * 32 + jc] = make_float2(o[jt][2], o[jt][3]);
        }
    }
    for (int i = tid; i < 2048; i += 256) wa_s[i] = Wattn[i];
    __syncthreads();

    // epilogue: 2 threads per query, each covers 32 output channels
    int q = tid & 127;
    int half = tid >> 7;
    float av[32];
    {
        const float4* os = (const float4*)&o_s[q * 32];
        float inv = sigma[0] / lsum_s[q];
#pragma unroll
        for (int i = 0; i < 8; i++) {
            float4 v = os[i];
            av[i * 4 + 0] = v.x * inv; av[i * 4 + 1] = v.y * inv;
            av[i * 4 + 2] = v.z * inv; av[i * 4 + 3] = v.w * inv;
        }
    }
    ULL acc[16];
#pragma unroll
    for (int i = 0; i < 16; i++) acc[i] = f2_pack(av[2 * i], av[2 * i + 1]);

    int n = qbase + q;
    int co0 = half * 32;
    const float* xp = x + ((size_t)b * Cv + co0) * Nv + n;
    float* op = out + ((size_t)b * Cv + co0) * Nv + n;
    const ulonglong2* wa_u = (const ulonglong2*)wa_s;
#pragma unroll 4
    for (int c = 0; c < 32; c++) {
        const ulonglong2* wr = wa_u + (size_t)(co0 + c) * 8;
        ULL d2 = 0ULL;
#pragma unroll
        for (int jj = 0; jj < 8; jj++) {
            ulonglong2 wv = wr[jj];
            d2 = f2_fma(acc[jj * 2 + 0], wv.x, d2);
            d2 = f2_fma(acc[jj * 2 + 1], wv.y, d2);
        }
        float2 df = f2_unpack(d2);
        op[(size_t)c * Nv] = xp[(size_t)c * Nv] + (df.x + df.y);
    }
}

// ======================================================================
// launch
// ======================================================================
extern "C" void kernel_launch(void* const* d_in, const int* in_sizes, int n_in,
                              void* d_out, int out_size) {
    const float* x     = (const float*)d_in[0];
    const float* Wth   = (const float*)d_in[1];
    const float* Wphi  = (const float*)d_in[2];
    const float* Wg    = (const float*)d_in[3];
    const float* Wattn = (const float*)d_in[4];
    const float* sigma = (const float*)d_in[5];
    float* out = (float*)d_out;

    prep_kernel<<<dim3(24, Bv), 256>>>(x, Wth, Wphi, Wg);
    attn_kernel<<<dim3(Nv / 128, Bv), 256>>>(x, Wattn, sigma, out);
}

// round 7
// speedup vs baseline: 3.2255x; 1.1444x over previous
#include <cuda_runtime.h>
#include <cuda_fp16.h>

// ---------------- problem constants ----------------
#define Bv 16
#define Cv 64
#define Nv 4096
#define Mv 1024
#define LN2R 1.4426950408889634f

typedef unsigned long long ULL;

// ---------------- helpers ----------------
__device__ __forceinline__ ULL f2_fma(ULL a, ULL b, ULL c) {
    ULL d; asm("fma.rn.f32x2 %0, %1, %2, %3;" : "=l"(d) : "l"(a), "l"(b), "l"(c)); return d;
}
__device__ __forceinline__ ULL f2_pack(float lo, float hi) {
    ULL r;
    asm("mov.b64 %0, {%1, %2};" : "=l"(r)
        : "r"(__float_as_uint(lo)), "r"(__float_as_uint(hi)));
    return r;
}
__device__ __forceinline__ float2 f2_unpack(ULL v) {
    unsigned lo, hi;
    asm("mov.b64 {%0, %1}, %2;" : "=r"(lo), "=r"(hi) : "l"(v));
    return make_float2(__uint_as_float(lo), __uint_as_float(hi));
}
__device__ __forceinline__ float tf32r(float x) {
    float r; asm("cvt.rna.tf32.f32 %0, %1;" : "=f"(r) : "f"(x)); return r;
}
// pack (hi, lo) f32 -> f16x2 (first source -> upper half, same as bf16x2)
__device__ __forceinline__ unsigned cvt_f16x2(float hi, float lo) {
    unsigned r;
    asm("cvt.rn.f16x2.f32 %0, %1, %2;" : "=r"(r) : "f"(hi), "f"(lo));
    return r;
}
__device__ __forceinline__ unsigned ex2_f16x2(unsigned v) {
    unsigned r; asm("ex2.approx.f16x2 %0, %1;" : "=r"(r) : "r"(v)); return r;
}
__device__ __forceinline__ unsigned smem_u32(const void* p) {
    unsigned a;
    asm("{.reg .u64 t; cvta.to.shared.u64 t, %1; cvt.u32.u64 %0, t;}"
        : "=r"(a) : "l"(p));
    return a;
}
__device__ __forceinline__ void cpa16(unsigned dst, const void* src) {
    asm volatile("cp.async.cg.shared.global [%0], [%1], 16;"
                 :: "r"(dst), "l"(src));
}
#define CPA_COMMIT() asm volatile("cp.async.commit_group;" ::: "memory")
#define CPA_WAIT0()  asm volatile("cp.async.wait_group 0;" ::: "memory")

#define LDSM4(r, a) \
    asm volatile("ldmatrix.sync.aligned.m8n8.x4.shared.b16 {%0,%1,%2,%3},[%4];" \
        : "=r"((r)[0]), "=r"((r)[1]), "=r"((r)[2]), "=r"((r)[3]) : "r"(a))

// mma.sync m16n8k8 tf32
__device__ __forceinline__ void mma_qk(float d[4], const unsigned a[4],
                                       unsigned b0, unsigned b1) {
    asm("mma.sync.aligned.m16n8k8.row.col.f32.tf32.tf32.f32 "
        "{%0,%1,%2,%3},{%4,%5,%6,%7},{%8,%9},{%10,%11,%12,%13};"
        : "=f"(d[0]), "=f"(d[1]), "=f"(d[2]), "=f"(d[3])
        : "r"(a[0]), "r"(a[1]), "r"(a[2]), "r"(a[3]),
          "r"(b0), "r"(b1), "f"(0.f), "f"(0.f), "f"(0.f), "f"(0.f));
}
// mma.sync m16n8k16 f16 (accumulate in place, f32 accum)
__device__ __forceinline__ void mma_pv(float d[4], const unsigned a[4],
                                       unsigned b0, unsigned b1) {
    asm("mma.sync.aligned.m16n8k16.row.col.f32.f16.f16.f32 "
        "{%0,%1,%2,%3},{%4,%5,%6,%7},{%8,%9},{%0,%1,%2,%3};"
        : "+f"(d[0]), "+f"(d[1]), "+f"(d[2]), "+f"(d[3])
        : "r"(a[0]), "r"(a[1]), "r"(a[2]), "r"(a[3]), "r"(b0), "r"(b1));
}

// ---------------- scratch ----------------
__device__ float d_theta[Bv * Nv * 8];        // [b][n][k] tf32-rounded, *LN2R
__device__ float d_phi  [Bv * Mv * 8];        // [b][m][pairs (p,p+4)] tf32-rounded
__device__ __half d_gTh [Bv * 32 * Mv];       // [b][j][m] f16

// ======================================================================
// prep_kernel: theta (blocks 0..15) + phi/gT (blocks 16..23). 256 thr.
// f32x2-packed inner loops.
// ======================================================================
__global__ void __launch_bounds__(256)
prep_kernel(const float* __restrict__ x,
            const float* __restrict__ Wth,
            const float* __restrict__ Wphi,
            const float* __restrict__ Wg) {
    __shared__ float sm[512 + 2048 + 128 * 41];
    int tid = threadIdx.x;
    int b = blockIdx.y;

    if (blockIdx.x < 16) {
        // ------- theta: W transposed to [c][k] for paired loads -------
        float* Ws = sm;
        for (int i = tid; i < 512; i += 256) {
            int k = i >> 6, c = i & 63;
            Ws[c * 8 + k] = Wth[i];
        }
        __syncthreads();
        int n = blockIdx.x * 256 + tid;
        const float* xp = x + ((size_t)b * Cv) * Nv + n;
        ULL acc2[4] = {0ULL, 0ULL, 0ULL, 0ULL};
#pragma unroll
        for (int cc = 0; cc < 64; cc += 16) {
            float xv[16];
#pragma unroll
            for (int u = 0; u < 16; u++) xv[u] = xp[(size_t)(cc + u) * Nv];
#pragma unroll
            for (int u = 0; u < 16; u++) {
                ULL xx = f2_pack(xv[u], xv[u]);
                const ulonglong2* wr = (const ulonglong2*)&Ws[(cc + u) * 8];
                ulonglong2 w01 = wr[0], w23 = wr[1];
                acc2[0] = f2_fma(w01.x, xx, acc2[0]);
                acc2[1] = f2_fma(w01.y, xx, acc2[1]);
                acc2[2] = f2_fma(w23.x, xx, acc2[2]);
                acc2[3] = f2_fma(w23.y, xx, acc2[3]);
            }
        }
        float2 p0 = f2_unpack(acc2[0]), p1 = f2_unpack(acc2[1]);
        float2 p2 = f2_unpack(acc2[2]), p3 = f2_unpack(acc2[3]);
        float* dst = d_theta + ((size_t)(b * Nv + n)) * 8;
        ((float4*)dst)[0] = make_float4(tf32r(p0.x * LN2R), tf32r(p0.y * LN2R),
                                        tf32r(p1.x * LN2R), tf32r(p1.y * LN2R));
        ((float4*)dst)[1] = make_float4(tf32r(p2.x * LN2R), tf32r(p2.y * LN2R),
                                        tf32r(p3.x * LN2R), tf32r(p3.y * LN2R));
    } else {
        // ------- phi/g: packed accumulators -------
        float* Wpt = sm;          // [c][8]
        float* Wgt = sm + 512;    // [c][32]
        float* red = sm + 2560;   // [128][41]
        for (int i = tid; i < 512; i += 256) {
            int k = i >> 6, c = i & 63;
            Wpt[c * 8 + k] = Wphi[i];
        }
        for (int i = tid; i < 2048; i += 256) {
            int j = i >> 6, c = i & 63;
            Wgt[c * 32 + j] = Wg[i];
        }
        __syncthreads();

        int lm = tid & 127, half = tid >> 7;
        int m = (blockIdx.x - 16) * 128 + lm;
        int h2 = m >> 5, w2 = m & 31;
        int n0 = ((h2 << 1) + half) * 64 + (w2 << 1);
        const float* xb = x + ((size_t)b * Cv) * Nv;

        float bp[8], bg[32];
#pragma unroll
        for (int k = 0; k < 8; k++) bp[k] = -3.4e38f;
#pragma unroll
        for (int j = 0; j < 32; j++) bg[j] = -3.4e38f;

#pragma unroll 1
        for (int p = 0; p < 2; p++) {
            const float* xp = xb + n0 + p;
            ULL ap2[4], ag2[16];
#pragma unroll
            for (int k = 0; k < 4; k++) ap2[k] = 0ULL;
#pragma unroll
            for (int j = 0; j < 16; j++) ag2[j] = 0ULL;
#pragma unroll 8
            for (int c = 0; c < 64; c++) {
                float xv = xp[(size_t)c * Nv];
                ULL xx = f2_pack(xv, xv);
                const ulonglong2* wp = (const ulonglong2*)&Wpt[c * 8];
                ulonglong2 wp0 = wp[0], wp1 = wp[1];
                ap2[0] = f2_fma(wp0.x, xx, ap2[0]);
                ap2[1] = f2_fma(wp0.y, xx, ap2[1]);
                ap2[2] = f2_fma(wp1.x, xx, ap2[2]);
                ap2[3] = f2_fma(wp1.y, xx, ap2[3]);
                const ulonglong2* wg = (const ulonglong2*)&Wgt[c * 32];
#pragma unroll
                for (int q = 0; q < 8; q++) {
                    ulonglong2 wv = wg[q];
                    ag2[q * 2 + 0] = f2_fma(wv.x, xx, ag2[q * 2 + 0]);
                    ag2[q * 2 + 1] = f2_fma(wv.y, xx, ag2[q * 2 + 1]);
                }
            }
#pragma unroll
            for (int k = 0; k < 4; k++) {
                float2 v = f2_unpack(ap2[k]);
                bp[k * 2 + 0] = fmaxf(bp[k * 2 + 0], v.x);
                bp[k * 2 + 1] = fmaxf(bp[k * 2 + 1], v.y);
            }
#pragma unroll
            for (int j = 0; j < 16; j++) {
                float2 v = f2_unpack(ag2[j]);
                bg[j * 2 + 0] = fmaxf(bg[j * 2 + 0], v.x);
                bg[j * 2 + 1] = fmaxf(bg[j * 2 + 1], v.y);
            }
        }

        if (half) {
            float* r = red + lm * 41;
#pragma unroll
            for (int k = 0; k < 8; k++) r[k] = bp[k];
#pragma unroll
            for (int j = 0; j < 32; j++) r[8 + j] = bg[j];
        }
        __syncthreads();
        if (!half) {
            const float* r = red + lm * 41;
#pragma unroll
            for (int k = 0; k < 8; k++) bp[k] = fmaxf(bp[k], r[k]);
#pragma unroll
            for (int j = 0; j < 32; j++) bg[j] = fmaxf(bg[j], r[8 + j]);

            float* pd = d_phi + ((size_t)(b * Mv + m)) * 8;
            ((float4*)pd)[0] = make_float4(tf32r(bp[0]), tf32r(bp[4]),
                                           tf32r(bp[1]), tf32r(bp[5]));
            ((float4*)pd)[1] = make_float4(tf32r(bp[2]), tf32r(bp[6]),
                                           tf32r(bp[3]), tf32r(bp[7]));
#pragma unroll
            for (int j = 0; j < 32; j++)
                d_gTh[((size_t)(b * 32 + j)) * Mv + m] = __float2half(bg[j]);
        }
    }
}

// ======================================================================
// attn_kernel: 256 thr = 8 warps x 16q = 128 q/CTA. grid (32, B).
// cp.async double buffer; ldmatrix B-frags; f16x2 ex2; lsum via ones-mma.
// smem (25600B): phi dbuf [0:8192) | gt dbuf [8192:25600)
// epilogue overlay: o_s [0:16384) | wa [16384:24576) | lsum [24576:25088)
// ======================================================================
#define GT_PITCH 136   // f16 per row (272B)
#define ONES_F16X2 0x3C003C00u

__global__ void __launch_bounds__(256)
attn_kernel(const float* __restrict__ x,
            const float* __restrict__ Wattn,
            const float* __restrict__ sigma,
            float* __restrict__ out) {
    __shared__ __align__(16) char smraw[25600];
    unsigned sbase = smem_u32(smraw);

    int tid = threadIdx.x;
    int w = tid >> 5, l = tid & 31;
    int g = l >> 2, k4 = l & 3;
    int b = blockIdx.y;
    int qbase = blockIdx.x * 128;

    // theta A-frag: 16 queries per warp
    unsigned a[4];
    {
        const float* th = d_theta + ((size_t)(b * Nv + qbase + w * 16)) * 8;
        a[0] = __float_as_uint(th[g * 8 + k4]);
        a[1] = __float_as_uint(th[(g + 8) * 8 + k4]);
        a[2] = __float_as_uint(th[g * 8 + k4 + 4]);
        a[3] = __float_as_uint(th[(g + 8) * 8 + k4 + 4]);
    }

    float o[4][4];
#pragma unroll
    for (int jt = 0; jt < 4; jt++)
#pragma unroll
        for (int i = 0; i < 4; i++) o[jt][i] = 0.f;
    float oS[4] = {0.f, 0.f, 0.f, 0.f};   // ones-mma accumulator (row sums)

    const char* phi_g = (const char*)(d_phi + (size_t)b * (Mv * 8));
    const char* gt_g = (const char*)(d_gTh + (size_t)b * (32 * Mv));

    // ---- stage tile 0 into buffer 0 ----
    {
        cpa16(sbase + tid * 16, phi_g + tid * 16);
        int row0 = tid >> 4, c0 = tid & 15;
        cpa16(sbase + 8192 + row0 * 272 + c0 * 16,
              gt_g + (size_t)row0 * (Mv * 2) + c0 * 16);
        int i2 = tid + 256;
        int row1 = i2 >> 4, c1 = i2 & 15;
        cpa16(sbase + 8192 + row1 * 272 + c1 * 16,
              gt_g + (size_t)row1 * (Mv * 2) + c1 * 16);
        CPA_COMMIT();
    }

#pragma unroll 1
    for (int mt = 0; mt < 8; mt++) {
        CPA_WAIT0();
        __syncthreads();

        int buf = mt & 1;
        if (mt < 7) {
            int nb = buf ^ 1;
            unsigned pbase = sbase + nb * 4096;
            unsigned gbase = sbase + 8192 + nb * 8704;
            const char* psrc = phi_g + (size_t)(mt + 1) * 4096;
            const char* gsrc = gt_g + (size_t)(mt + 1) * 256;
            cpa16(pbase + tid * 16, psrc + tid * 16);
            int row0 = tid >> 4, c0 = tid & 15;
            cpa16(gbase + row0 * 272 + c0 * 16,
                  gsrc + (size_t)row0 * (Mv * 2) + c0 * 16);
            int i2 = tid + 256;
            int row1 = i2 >> 4, c1 = i2 & 15;
            cpa16(gbase + row1 * 272 + c1 * 16,
                  gsrc + (size_t)row1 * (Mv * 2) + c1 * 16);
            CPA_COMMIT();
        }

        const float* phi_b = (const float*)(smraw + buf * 4096);
        unsigned gt_lane = sbase + 8192 + buf * 8704 + (unsigned)l * 272;

#pragma unroll 4
        for (int ms = 0; ms < 8; ms++) {
            int m0 = ms * 16;
            float2 bb0 = *(const float2*)&phi_b[(m0 + g) * 8 + k4 * 2];
            float2 bb1 = *(const float2*)&phi_b[(m0 + 8 + g) * 8 + k4 * 2];

            float s0[4], s1[4];
            mma_qk(s0, a, __float_as_uint(bb0.x), __float_as_uint(bb0.y));
            mma_qk(s1, a, __float_as_uint(bb1.x), __float_as_uint(bb1.y));

            // P = 2^S in f16x2 directly (theta pre-scaled by 1/ln2)
            unsigned pa[4];
            pa[0] = ex2_f16x2(cvt_f16x2(s0[1], s0[0]));
            pa[1] = ex2_f16x2(cvt_f16x2(s0[3], s0[2]));
            pa[2] = ex2_f16x2(cvt_f16x2(s1[1], s1[0]));
            pa[3] = ex2_f16x2(cvt_f16x2(s1[3], s1[2]));

            unsigned bg0[4], bg1[4];
            LDSM4(bg0, gt_lane + m0 * 2);
            LDSM4(bg1, gt_lane + m0 * 2 + 16);

#pragma unroll
            for (int jt = 0; jt < 4; jt++) mma_pv(o[jt], pa, bg0[jt], bg1[jt]);
            mma_pv(oS, pa, ONES_F16X2, ONES_F16X2);   // row sums
        }
    }

    __syncthreads();   // all tile compute done; overlay epilogue arrays
    float* o_s = (float*)smraw;                 // [128][32]
    float* wa_s = (float*)(smraw + 16384);      // [2048]
    float* lsum_s = (float*)(smraw + 24576);    // [128]

    if (k4 == 0) {
        lsum_s[w * 16 + g] = oS[0];        // query row g
        lsum_s[w * 16 + g + 8] = oS[2];    // query row g+8
    }
    {
        int q0 = w * 16;
#pragma unroll
        for (int jt = 0; jt < 4; jt++) {
            int jc = jt * 8 + 2 * k4;
            *(float2*)&o_s[(q0 + g) * 32 + jc] = make_float2(o[jt][0], o[jt][1]);
            *(float2*)&o_s[(q0 + g + 8) * 32 + jc] = make_float2(o[jt][2], o[jt][3]);
        }
    }
    for (int i = tid; i < 2048; i += 256) wa_s[i] = Wattn[i];
    __syncthreads();

    // epilogue: 2 threads per query, 32 output channels each
    int q = tid & 127;
    int half = tid >> 7;
    float av[32];
    {
        const float4* os = (const float4*)&o_s[q * 32];
        float inv = sigma[0] / lsum_s[q];
#pragma unroll
        for (int i = 0; i < 8; i++) {
            float4 v = os[i];
            av[i * 4 + 0] = v.x * inv; av[i * 4 + 1] = v.y * inv;
            av[i * 4 + 2] = v.z * inv; av[i * 4 + 3] = v.w * inv;
        }
    }
    ULL acc[16];
#pragma unroll
    for (int i = 0; i < 16; i++) acc[i] = f2_pack(av[2 * i], av[2 * i + 1]);

    int n = qbase + q;
    int co0 = half * 32;
    const float* xp = x + ((size_t)b * Cv + co0) * Nv + n;
    float* op = out + ((size_t)b * Cv + co0) * Nv + n;
    const ulonglong2* wa_u = (const ulonglong2*)wa_s;
#pragma unroll 4
    for (int c = 0; c < 32; c++) {
        const ulonglong2* wr = wa_u + (size_t)(co0 + c) * 8;
        ULL d2 = 0ULL;
#pragma unroll
        for (int jj = 0; jj < 8; jj++) {
            ulonglong2 wv = wr[jj];
            d2 = f2_fma(acc[jj * 2 + 0], wv.x, d2);
            d2 = f2_fma(acc[jj * 2 + 1], wv.y, d2);
        }
        float2 df = f2_unpack(d2);
        op[(size_t)c * Nv] = xp[(size_t)c * Nv] + (df.x + df.y);
    }
}

// ======================================================================
// launch
// ======================================================================
extern "C" void kernel_launch(void* const* d_in, const int* in_sizes, int n_in,
                              void* d_out, int out_size) {
    const float* x     = (const float*)d_in[0];
    const float* Wth   = (const float*)d_in[1];
    const float* Wphi  = (const float*)d_in[2];
    const float* Wg    = (const float*)d_in[3];
    const float* Wattn = (const float*)d_in[4];
    const float* sigma = (const float*)d_in[5];
    float* out = (float*)d_out;

    prep_kernel<<<dim3(24, Bv), 256>>>(x, Wth, Wphi, Wg);
    attn_kernel<<<dim3(Nv / 128, Bv), 256>>>(x, Wattn, sigma, out);
}

// round 8
// speedup vs baseline: 3.8613x; 1.1971x over previous
#include <cuda_runtime.h>
#include <cuda_fp16.h>

// ---------------- problem constants ----------------
#define Bv 16
#define Cv 64
#define Nv 4096
#define Mv 1024
#define LN2R 1.4426950408889634f

typedef unsigned long long ULL;

// ---------------- helpers ----------------
__device__ __forceinline__ ULL f2_fma(ULL a, ULL b, ULL c) {
    ULL d; asm("fma.rn.f32x2 %0, %1, %2, %3;" : "=l"(d) : "l"(a), "l"(b), "l"(c)); return d;
}
__device__ __forceinline__ ULL f2_pack(float lo, float hi) {
    ULL r;
    asm("mov.b64 %0, {%1, %2};" : "=l"(r)
        : "r"(__float_as_uint(lo)), "r"(__float_as_uint(hi)));
    return r;
}
__device__ __forceinline__ float2 f2_unpack(ULL v) {
    unsigned lo, hi;
    asm("mov.b64 {%0, %1}, %2;" : "=r"(lo), "=r"(hi) : "l"(v));
    return make_float2(__uint_as_float(lo), __uint_as_float(hi));
}
__device__ __forceinline__ float tf32r(float x) {
    float r; asm("cvt.rna.tf32.f32 %0, %1;" : "=f"(r) : "f"(x)); return r;
}
__device__ __forceinline__ unsigned cvt_f16x2(float hi, float lo) {
    unsigned r;
    asm("cvt.rn.f16x2.f32 %0, %1, %2;" : "=r"(r) : "f"(hi), "f"(lo));
    return r;
}
__device__ __forceinline__ unsigned ex2_f16x2(unsigned v) {
    unsigned r; asm("ex2.approx.f16x2 %0, %1;" : "=r"(r) : "r"(v)); return r;
}
__device__ __forceinline__ unsigned smem_u32(const void* p) {
    unsigned a;
    asm("{.reg .u64 t; cvta.to.shared.u64 t, %1; cvt.u32.u64 %0, t;}"
        : "=r"(a) : "l"(p));
    return a;
}
__device__ __forceinline__ void cpa16(unsigned dst, const void* src) {
    asm volatile("cp.async.cg.shared.global [%0], [%1], 16;"
                 :: "r"(dst), "l"(src));
}
#define CPA_COMMIT() asm volatile("cp.async.commit_group;" ::: "memory")
#define CPA_WAIT0()  asm volatile("cp.async.wait_group 0;" ::: "memory")

#define LDSM4(r, a) \
    asm volatile("ldmatrix.sync.aligned.m8n8.x4.shared.b16 {%0,%1,%2,%3},[%4];" \
        : "=r"((r)[0]), "=r"((r)[1]), "=r"((r)[2]), "=r"((r)[3]) : "r"(a))

// mma.sync m16n8k8 tf32
__device__ __forceinline__ void mma_qk(float d[4], const unsigned a[4],
                                       unsigned b0, unsigned b1) {
    asm("mma.sync.aligned.m16n8k8.row.col.f32.tf32.tf32.f32 "
        "{%0,%1,%2,%3},{%4,%5,%6,%7},{%8,%9},{%10,%11,%12,%13};"
        : "=f"(d[0]), "=f"(d[1]), "=f"(d[2]), "=f"(d[3])
        : "r"(a[0]), "r"(a[1]), "r"(a[2]), "r"(a[3]),
          "r"(b0), "r"(b1), "f"(0.f), "f"(0.f), "f"(0.f), "f"(0.f));
}
// mma.sync m16n8k16 f16 (accumulate in place, f32 accum)
__device__ __forceinline__ void mma_pv(float d[4], const unsigned a[4],
                                       unsigned b0, unsigned b1) {
    asm("mma.sync.aligned.m16n8k16.row.col.f32.f16.f16.f32 "
        "{%0,%1,%2,%3},{%4,%5,%6,%7},{%8,%9},{%0,%1,%2,%3};"
        : "+f"(d[0]), "+f"(d[1]), "+f"(d[2]), "+f"(d[3])
        : "r"(a[0]), "r"(a[1]), "r"(a[2]), "r"(a[3]), "r"(b0), "r"(b1));
}

// ---------------- scratch ----------------
__device__ float d_theta[Bv * Nv * 8];        // [b][n][k] tf32-rounded, *LN2R
__device__ float d_phi  [Bv * Mv * 8];        // [b][m][pairs (p,p+4)] tf32-rounded
__device__ __half d_gTh [Bv * 32 * Mv];       // [b][j][m] f16

// ======================================================================
// prep_kernel (fused, single pass over x): grid (8, B), 256 threads.
// thread = (lm = m within block's 128, half = pool row). Each thread
// loads float2 (two adjacent cols) per channel and accumulates
// theta(both pixels) + phi + g with output-paired f32x2 accumulators.
// Weights cached per-c in registers via 12 LDS.128.
// ======================================================================
__global__ void __launch_bounds__(256)
prep_kernel(const float* __restrict__ x,
            const float* __restrict__ Wth,
            const float* __restrict__ Wphi,
            const float* __restrict__ Wg) {
    __shared__ float Wt[64 * 48];        // [c][0:8)=theta [8:16)=phi [16:48)=g
    __shared__ float red[128 * 41];      // cross-half pool reduce

    int tid = threadIdx.x;
    int b = blockIdx.y;

    for (int i = tid; i < 512; i += 256) {
        int k = i >> 6, c = i & 63;
        Wt[c * 48 + k] = Wth[i];
        Wt[c * 48 + 8 + k] = Wphi[i];
    }
    for (int i = tid; i < 2048; i += 256) {
        int j = i >> 6, c = i & 63;
        Wt[c * 48 + 16 + j] = Wg[i];
    }
    __syncthreads();

    int lm = tid & 127, half = tid >> 7;
    int m = blockIdx.x * 128 + lm;
    int h2 = m >> 5, w2 = m & 31;
    int n0 = ((h2 << 1) + half) * 64 + (w2 << 1);
    const float* xb = x + ((size_t)b * Cv) * Nv + n0;

    // acc[p][0:4)=theta, [4:8)=phi, [8:24)=g  (output-paired f32x2)
    ULL acc0[24], acc1[24];
#pragma unroll
    for (int i = 0; i < 24; i++) { acc0[i] = 0ULL; acc1[i] = 0ULL; }

#pragma unroll 8
    for (int c = 0; c < 64; c++) {
        float2 xv = *(const float2*)(xb + (size_t)c * Nv);
        ULL xx0 = f2_pack(xv.x, xv.x);
        ULL xx1 = f2_pack(xv.y, xv.y);
        const ulonglong2* wr = (const ulonglong2*)&Wt[c * 48];
#pragma unroll
        for (int i = 0; i < 12; i++) {
            ulonglong2 wv = wr[i];
            acc0[2 * i]     = f2_fma(wv.x, xx0, acc0[2 * i]);
            acc0[2 * i + 1] = f2_fma(wv.y, xx0, acc0[2 * i + 1]);
            acc1[2 * i]     = f2_fma(wv.x, xx1, acc1[2 * i]);
            acc1[2 * i + 1] = f2_fma(wv.y, xx1, acc1[2 * i + 1]);
        }
    }

    // ---- theta: write both pixels directly ----
    {
        float t0[8], t1[8];
#pragma unroll
        for (int i = 0; i < 4; i++) {
            float2 v0 = f2_unpack(acc0[i]);
            float2 v1 = f2_unpack(acc1[i]);
            t0[2 * i] = v0.x; t0[2 * i + 1] = v0.y;
            t1[2 * i] = v1.x; t1[2 * i + 1] = v1.y;
        }
        float* d0 = d_theta + ((size_t)(b * Nv + n0)) * 8;
        ((float4*)d0)[0] = make_float4(tf32r(t0[0] * LN2R), tf32r(t0[1] * LN2R),
                                       tf32r(t0[2] * LN2R), tf32r(t0[3] * LN2R));
        ((float4*)d0)[1] = make_float4(tf32r(t0[4] * LN2R), tf32r(t0[5] * LN2R),
                                       tf32r(t0[6] * LN2R), tf32r(t0[7] * LN2R));
        float* d1 = d_theta + ((size_t)(b * Nv + n0 + 1)) * 8;
        ((float4*)d1)[0] = make_float4(tf32r(t1[0] * LN2R), tf32r(t1[1] * LN2R),
                                       tf32r(t1[2] * LN2R), tf32r(t1[3] * LN2R));
        ((float4*)d1)[1] = make_float4(tf32r(t1[4] * LN2R), tf32r(t1[5] * LN2R),
                                       tf32r(t1[6] * LN2R), tf32r(t1[7] * LN2R));
    }

    // ---- phi/g: max over the two cols, then cross-half reduce ----
    float bp[8], bg[32];
#pragma unroll
    for (int i = 0; i < 4; i++) {
        float2 v0 = f2_unpack(acc0[4 + i]);
        float2 v1 = f2_unpack(acc1[4 + i]);
        bp[2 * i] = fmaxf(v0.x, v1.x);
        bp[2 * i + 1] = fmaxf(v0.y, v1.y);
    }
#pragma unroll
    for (int i = 0; i < 16; i++) {
        float2 v0 = f2_unpack(acc0[8 + i]);
        float2 v1 = f2_unpack(acc1[8 + i]);
        bg[2 * i] = fmaxf(v0.x, v1.x);
        bg[2 * i + 1] = fmaxf(v0.y, v1.y);
    }

    if (half) {
        float* r = red + lm * 41;
#pragma unroll
        for (int k = 0; k < 8; k++) r[k] = bp[k];
#pragma unroll
        for (int j = 0; j < 32; j++) r[8 + j] = bg[j];
    }
    __syncthreads();
    if (!half) {
        const float* r = red + lm * 41;
#pragma unroll
        for (int k = 0; k < 8; k++) bp[k] = fmaxf(bp[k], r[k]);
#pragma unroll
        for (int j = 0; j < 32; j++) bg[j] = fmaxf(bg[j], r[8 + j]);

        float* pd = d_phi + ((size_t)(b * Mv + m)) * 8;
        ((float4*)pd)[0] = make_float4(tf32r(bp[0]), tf32r(bp[4]),
                                       tf32r(bp[1]), tf32r(bp[5]));
        ((float4*)pd)[1] = make_float4(tf32r(bp[2]), tf32r(bp[6]),
                                       tf32r(bp[3]), tf32r(bp[7]));
#pragma unroll
        for (int j = 0; j < 32; j++)
            d_gTh[((size_t)(b * 32 + j)) * Mv + m] = __float2half(bg[j]);
    }
}

// ======================================================================
// attn_kernel: 256 thr = 8 warps x 16q. grid (32, B).
// 2-stage software pipeline: QK/ex2 of step ms+1 overlaps PV of step ms.
// ======================================================================
#define GT_PITCH 136
#define ONES_F16X2 0x3C003C00u

#define COMPUTE_PA(pa, m0) do {                                              \
    float2 bb0 = *(const float2*)&phi_b[((m0) + g) * 8 + k4 * 2];            \
    float2 bb1 = *(const float2*)&phi_b[((m0) + 8 + g) * 8 + k4 * 2];        \
    float s0[4], s1[4];                                                      \
    mma_qk(s0, a, __float_as_uint(bb0.x), __float_as_uint(bb0.y));           \
    mma_qk(s1, a, __float_as_uint(bb1.x), __float_as_uint(bb1.y));           \
    (pa)[0] = ex2_f16x2(cvt_f16x2(s0[1], s0[0]));                            \
    (pa)[1] = ex2_f16x2(cvt_f16x2(s0[3], s0[2]));                            \
    (pa)[2] = ex2_f16x2(cvt_f16x2(s1[1], s1[0]));                            \
    (pa)[3] = ex2_f16x2(cvt_f16x2(s1[3], s1[2]));                            \
} while (0)

__global__ void __launch_bounds__(256)
attn_kernel(const float* __restrict__ x,
            const float* __restrict__ Wattn,
            const float* __restrict__ sigma,
            float* __restrict__ out) {
    __shared__ __align__(16) char smraw[25600];
    unsigned sbase = smem_u32(smraw);

    int tid = threadIdx.x;
    int w = tid >> 5, l = tid & 31;
    int g = l >> 2, k4 = l & 3;
    int b = blockIdx.y;
    int qbase = blockIdx.x * 128;

    unsigned a[4];
    {
        const float* th = d_theta + ((size_t)(b * Nv + qbase + w * 16)) * 8;
        a[0] = __float_as_uint(th[g * 8 + k4]);
        a[1] = __float_as_uint(th[(g + 8) * 8 + k4]);
        a[2] = __float_as_uint(th[g * 8 + k4 + 4]);
        a[3] = __float_as_uint(th[(g + 8) * 8 + k4 + 4]);
    }

    float o[4][4];
#pragma unroll
    for (int jt = 0; jt < 4; jt++)
#pragma unroll
        for (int i = 0; i < 4; i++) o[jt][i] = 0.f;
    float oS[4] = {0.f, 0.f, 0.f, 0.f};

    const char* phi_g = (const char*)(d_phi + (size_t)b * (Mv * 8));
    const char* gt_g = (const char*)(d_gTh + (size_t)b * (32 * Mv));

    // stage tile 0 into buffer 0
    {
        cpa16(sbase + tid * 16, phi_g + tid * 16);
        int row0 = tid >> 4, c0 = tid & 15;
        cpa16(sbase + 8192 + row0 * 272 + c0 * 16,
              gt_g + (size_t)row0 * (Mv * 2) + c0 * 16);
        int i2 = tid + 256;
        int row1 = i2 >> 4, c1 = i2 & 15;
        cpa16(sbase + 8192 + row1 * 272 + c1 * 16,
              gt_g + (size_t)row1 * (Mv * 2) + c1 * 16);
        CPA_COMMIT();
    }

#pragma unroll 1
    for (int mt = 0; mt < 8; mt++) {
        CPA_WAIT0();
        __syncthreads();

        int buf = mt & 1;
        if (mt < 7) {
            int nb = buf ^ 1;
            unsigned pbase = sbase + nb * 4096;
            unsigned gbase = sbase + 8192 + nb * 8704;
            const char* psrc = phi_g + (size_t)(mt + 1) * 4096;
            const char* gsrc = gt_g + (size_t)(mt + 1) * 256;
            cpa16(pbase + tid * 16, psrc + tid * 16);
            int row0 = tid >> 4, c0 = tid & 15;
            cpa16(gbase + row0 * 272 + c0 * 16,
                  gsrc + (size_t)row0 * (Mv * 2) + c0 * 16);
            int i2 = tid + 256;
            int row1 = i2 >> 4, c1 = i2 & 15;
            cpa16(gbase + row1 * 272 + c1 * 16,
                  gsrc + (size_t)row1 * (Mv * 2) + c1 * 16);
            CPA_COMMIT();
        }

        const float* phi_b = (const float*)(smraw + buf * 4096);
        unsigned gt_lane = sbase + 8192 + buf * 8704 + (unsigned)l * 272;

        // software pipeline: paC = current step's P, paN = next step's
        unsigned paC[4], paN[4];
        COMPUTE_PA(paC, 0);
#pragma unroll
        for (int ms = 0; ms < 8; ms++) {
            unsigned bg0[4], bg1[4];
            LDSM4(bg0, gt_lane + ms * 32);
            LDSM4(bg1, gt_lane + ms * 32 + 16);
            if (ms < 7) COMPUTE_PA(paN, (ms + 1) * 16);
#pragma unroll
            for (int jt = 0; jt < 4; jt++) mma_pv(o[jt], paC, bg0[jt], bg1[jt]);
            mma_pv(oS, paC, ONES_F16X2, ONES_F16X2);
#pragma unroll
            for (int i = 0; i < 4; i++) paC[i] = paN[i];
        }
    }

    __syncthreads();   // tile compute done; overlay epilogue arrays
    float* o_s = (float*)smraw;                 // [128][32]
    float* wa_s = (float*)(smraw + 16384);      // [2048]
    float* lsum_s = (float*)(smraw + 24576);    // [128]

    if (k4 == 0) {
        lsum_s[w * 16 + g] = oS[0];
        lsum_s[w * 16 + g + 8] = oS[2];
    }
    {
        int q0 = w * 16;
#pragma unroll
        for (int jt = 0; jt < 4; jt++) {
            int jc = jt * 8 + 2 * k4;
            *(float2*)&o_s[(q0 + g) * 32 + jc] = make_float2(o[jt][0], o[jt][1]);
            *(float2*)&o_s[(q0 + g + 8) * 32 + jc] = make_float2(o[jt][2], o[jt][3]);
        }
    }
    for (int i = tid; i < 2048; i += 256) wa_s[i] = Wattn[i];
    __syncthreads();

    // epilogue: 2 threads per query, 32 output channels each
    int q = tid & 127;
    int half = tid >> 7;
    float av[32];
    {
        const float4* os = (const float4*)&o_s[q * 32];
        float inv = sigma[0] / lsum_s[q];
#pragma unroll
        for (int i = 0; i < 8; i++) {
            float4 v = os[i];
            av[i * 4 + 0] = v.x * inv; av[i * 4 + 1] = v.y * inv;
            av[i * 4 + 2] = v.z * inv; av[i * 4 + 3] = v.w * inv;
        }
    }
    ULL acc[16];
#pragma unroll
    for (int i = 0; i < 16; i++) acc[i] = f2_pack(av[2 * i], av[2 * i + 1]);

    int n = qbase + q;
    int co0 = half * 32;
    const float* xp = x + ((size_t)b * Cv + co0) * Nv + n;
    float* op = out + ((size_t)b * Cv + co0) * Nv + n;
    const ulonglong2* wa_u = (const ulonglong2*)wa_s;
#pragma unroll 4
    for (int c = 0; c < 32; c++) {
        const ulonglong2* wr = wa_u + (size_t)(co0 + c) * 8;
        ULL d2 = 0ULL;
#pragma unroll
        for (int jj = 0; jj < 8; jj++) {
            ulonglong2 wv = wr[jj];
            d2 = f2_fma(acc[jj * 2 + 0], wv.x, d2);
            d2 = f2_fma(acc[jj * 2 + 1], wv.y, d2);
        }
        float2 df = f2_unpack(d2);
        op[(size_t)c * Nv] = xp[(size_t)c * Nv] + (df.x + df.y);
    }
}

// ======================================================================
// launch
// ======================================================================
extern "C" void kernel_launch(void* const* d_in, const int* in_sizes, int n_in,
                              void* d_out, int out_size) {
    const float* x     = (const float*)d_in[0];
    const float* Wth   = (const float*)d_in[1];
    const float* Wphi  = (const float*)d_in[2];
    const float* Wg    = (const float*)d_in[3];
    const float* Wattn = (const float*)d_in[4];
    const float* sigma = (const float*)d_in[5];
    float* out = (float*)d_out;

    prep_kernel<<<dim3(8, Bv), 256>>>(x, Wth, Wphi, Wg);
    attn_kernel<<<dim3(Nv / 128, Bv), 256>>>(x, Wattn, sigma, out);
}

// round 10
// speedup vs baseline: 4.1362x; 1.0712x over previous
#include <cuda_runtime.h>
#include <cuda_fp16.h>

// ---------------- problem constants ----------------
#define Bv 16
#define Cv 64
#define Nv 4096
#define Mv 1024
#define LN2R 1.4426950408889634f

typedef unsigned long long ULL;

// ---------------- helpers ----------------
__device__ __forceinline__ ULL f2_fma(ULL a, ULL b, ULL c) {
    ULL d; asm("fma.rn.f32x2 %0, %1, %2, %3;" : "=l"(d) : "l"(a), "l"(b), "l"(c)); return d;
}
__device__ __forceinline__ ULL f2_pack(float lo, float hi) {
    ULL r;
    asm("mov.b64 %0, {%1, %2};" : "=l"(r)
        : "r"(__float_as_uint(lo)), "r"(__float_as_uint(hi)));
    return r;
}
__device__ __forceinline__ float2 f2_unpack(ULL v) {
    unsigned lo, hi;
    asm("mov.b64 {%0, %1}, %2;" : "=r"(lo), "=r"(hi) : "l"(v));
    return make_float2(__uint_as_float(lo), __uint_as_float(hi));
}
__device__ __forceinline__ float tf32r(float x) {
    float r; asm("cvt.rna.tf32.f32 %0, %1;" : "=f"(r) : "f"(x)); return r;
}
__device__ __forceinline__ unsigned cvt_f16x2(float hi, float lo) {
    unsigned r;
    asm("cvt.rn.f16x2.f32 %0, %1, %2;" : "=r"(r) : "f"(hi), "f"(lo));
    return r;
}
__device__ __forceinline__ unsigned ex2_f16x2(unsigned v) {
    unsigned r; asm("ex2.approx.f16x2 %0, %1;" : "=r"(r) : "r"(v)); return r;
}
__device__ __forceinline__ unsigned smem_u32(const void* p) {
    unsigned a;
    asm("{.reg .u64 t; cvta.to.shared.u64 t, %1; cvt.u32.u64 %0, t;}"
        : "=r"(a) : "l"(p));
    return a;
}
__device__ __forceinline__ void cpa16(unsigned dst, const void* src) {
    asm volatile("cp.async.cg.shared.global [%0], [%1], 16;"
                 :: "r"(dst), "l"(src));
}
#define CPA_COMMIT() asm volatile("cp.async.commit_group;" ::: "memory")
#define CPA_WAIT0()  asm volatile("cp.async.wait_group 0;" ::: "memory")

#define LDSM4(r, a) \
    asm volatile("ldmatrix.sync.aligned.m8n8.x4.shared.b16 {%0,%1,%2,%3},[%4];" \
        : "=r"((r)[0]), "=r"((r)[1]), "=r"((r)[2]), "=r"((r)[3]) : "r"(a))

// mma.sync m16n8k8 tf32
__device__ __forceinline__ void mma_qk(float d[4], const unsigned a[4],
                                       unsigned b0, unsigned b1) {
    asm("mma.sync.aligned.m16n8k8.row.col.f32.tf32.tf32.f32 "
        "{%0,%1,%2,%3},{%4,%5,%6,%7},{%8,%9},{%10,%11,%12,%13};"
        : "=f"(d[0]), "=f"(d[1]), "=f"(d[2]), "=f"(d[3])
        : "r"(a[0]), "r"(a[1]), "r"(a[2]), "r"(a[3]),
          "r"(b0), "r"(b1), "f"(0.f), "f"(0.f), "f"(0.f), "f"(0.f));
}
// mma.sync m16n8k16 f16 (accumulate in place, f32 accum)
__device__ __forceinline__ void mma_pv(float d[4], const unsigned a[4],
                                       unsigned b0, unsigned b1) {
    asm("mma.sync.aligned.m16n8k16.row.col.f32.f16.f16.f32 "
        "{%0,%1,%2,%3},{%4,%5,%6,%7},{%8,%9},{%0,%1,%2,%3};"
        : "+f"(d[0]), "+f"(d[1]), "+f"(d[2]), "+f"(d[3])
        : "r"(a[0]), "r"(a[1]), "r"(a[2]), "r"(a[3]), "r"(b0), "r"(b1));
}

// ---------------- scratch ----------------
__device__ float d_theta[Bv * Nv * 8];        // [b][n][k] tf32-rounded, *LN2R
__device__ float d_phi  [Bv * Mv * 8];        // [b][m][pairs (p,p+4)] tf32-rounded
__device__ __half d_gTh [Bv * 32 * Mv];       // [b][j][m] f16

// ======================================================================
// prep_kernel (fused, single pass over x): grid (8, B), 256 threads.
// ======================================================================
__global__ void __launch_bounds__(256)
prep_kernel(const float* __restrict__ x,
            const float* __restrict__ Wth,
            const float* __restrict__ Wphi,
            const float* __restrict__ Wg) {
    __shared__ float Wt[64 * 48];        // [c][0:8)=theta [8:16)=phi [16:48)=g
    __shared__ float red[128 * 41];

    int tid = threadIdx.x;
    int b = blockIdx.y;

    for (int i = tid; i < 512; i += 256) {
        int k = i >> 6, c = i & 63;
        Wt[c * 48 + k] = Wth[i];
        Wt[c * 48 + 8 + k] = Wphi[i];
    }
    for (int i = tid; i < 2048; i += 256) {
        int j = i >> 6, c = i & 63;
        Wt[c * 48 + 16 + j] = Wg[i];
    }
    __syncthreads();

    int lm = tid & 127, half = tid >> 7;
    int m = blockIdx.x * 128 + lm;
    int h2 = m >> 5, w2 = m & 31;
    int n0 = ((h2 << 1) + half) * 64 + (w2 << 1);
    const float* xb = x + ((size_t)b * Cv) * Nv + n0;

    ULL acc0[24], acc1[24];
#pragma unroll
    for (int i = 0; i < 24; i++) { acc0[i] = 0ULL; acc1[i] = 0ULL; }

#pragma unroll 8
    for (int c = 0; c < 64; c++) {
        float2 xv = *(const float2*)(xb + (size_t)c * Nv);
        ULL xx0 = f2_pack(xv.x, xv.x);
        ULL xx1 = f2_pack(xv.y, xv.y);
        const ulonglong2* wr = (const ulonglong2*)&Wt[c * 48];
#pragma unroll
        for (int i = 0; i < 12; i++) {
            ulonglong2 wv = wr[i];
            acc0[2 * i]     = f2_fma(wv.x, xx0, acc0[2 * i]);
            acc0[2 * i + 1] = f2_fma(wv.y, xx0, acc0[2 * i + 1]);
            acc1[2 * i]     = f2_fma(wv.x, xx1, acc1[2 * i]);
            acc1[2 * i + 1] = f2_fma(wv.y, xx1, acc1[2 * i + 1]);
        }
    }

    {
        float t0[8], t1[8];
#pragma unroll
        for (int i = 0; i < 4; i++) {
            float2 v0 = f2_unpack(acc0[i]);
            float2 v1 = f2_unpack(acc1[i]);
            t0[2 * i] = v0.x; t0[2 * i + 1] = v0.y;
            t1[2 * i] = v1.x; t1[2 * i + 1] = v1.y;
        }
        float* d0 = d_theta + ((size_t)(b * Nv + n0)) * 8;
        ((float4*)d0)[0] = make_float4(tf32r(t0[0] * LN2R), tf32r(t0[1] * LN2R),
                                       tf32r(t0[2] * LN2R), tf32r(t0[3] * LN2R));
        ((float4*)d0)[1] = make_float4(tf32r(t0[4] * LN2R), tf32r(t0[5] * LN2R),
                                       tf32r(t0[6] * LN2R), tf32r(t0[7] * LN2R));
        float* d1 = d_theta + ((size_t)(b * Nv + n0 + 1)) * 8;
        ((float4*)d1)[0] = make_float4(tf32r(t1[0] * LN2R), tf32r(t1[1] * LN2R),
                                       tf32r(t1[2] * LN2R), tf32r(t1[3] * LN2R));
        ((float4*)d1)[1] = make_float4(tf32r(t1[4] * LN2R), tf32r(t1[5] * LN2R),
                                       tf32r(t1[6] * LN2R), tf32r(t1[7] * LN2R));
    }

    float bp[8], bg[32];
#pragma unroll
    for (int i = 0; i < 4; i++) {
        float2 v0 = f2_unpack(acc0[4 + i]);
        float2 v1 = f2_unpack(acc1[4 + i]);
        bp[2 * i] = fmaxf(v0.x, v1.x);
        bp[2 * i + 1] = fmaxf(v0.y, v1.y);
    }
#pragma unroll
    for (int i = 0; i < 16; i++) {
        float2 v0 = f2_unpack(acc0[8 + i]);
        float2 v1 = f2_unpack(acc1[8 + i]);
        bg[2 * i] = fmaxf(v0.x, v1.x);
        bg[2 * i + 1] = fmaxf(v0.y, v1.y);
    }

    if (half) {
        float* r = red + lm * 41;
#pragma unroll
        for (int k = 0; k < 8; k++) r[k] = bp[k];
#pragma unroll
        for (int j = 0; j < 32; j++) r[8 + j] = bg[j];
    }
    __syncthreads();
    if (!half) {
        const float* r = red + lm * 41;
#pragma unroll
        for (int k = 0; k < 8; k++) bp[k] = fmaxf(bp[k], r[k]);
#pragma unroll
        for (int j = 0; j < 32; j++) bg[j] = fmaxf(bg[j], r[8 + j]);

        float* pd = d_phi + ((size_t)(b * Mv + m)) * 8;
        ((float4*)pd)[0] = make_float4(tf32r(bp[0]), tf32r(bp[4]),
                                       tf32r(bp[1]), tf32r(bp[5]));
        ((float4*)pd)[1] = make_float4(tf32r(bp[2]), tf32r(bp[6]),
                                       tf32r(bp[3]), tf32r(bp[7]));
#pragma unroll
        for (int j = 0; j < 32; j++)
            d_gTh[((size_t)(b * 32 + j)) * Mv + m] = __float2half(bg[j]);
    }
}

// ======================================================================
// attn_kernel: 128 thr = 4 warps x 32q = 128 q/CTA. grid (32, B).
// Two A-frags per warp share every phi/g B-frag -> smem traffic halved.
// smem (25600B): phi dbuf [0:8192) | gt dbuf [8192:25600)
// epilogue overlay: o_s [0:16384) | wa [16384:24576) | lsum [24576:25088)
// ======================================================================
#define GT_PITCH 136
#define ONES_F16X2 0x3C003C00u

__global__ void __launch_bounds__(128, 4)
attn_kernel(const float* __restrict__ x,
            const float* __restrict__ Wattn,
            const float* __restrict__ sigma,
            float* __restrict__ out) {
    __shared__ __align__(16) char smraw[25600];
    unsigned sbase = smem_u32(smraw);

    int tid = threadIdx.x;
    int w = tid >> 5, l = tid & 31;
    int g = l >> 2, k4 = l & 3;
    int b = blockIdx.y;
    int qbase = blockIdx.x * 128;

    // two theta A-frags: queries [w*32, w*32+16) and [w*32+16, w*32+32)
    unsigned aA[4], aB[4];
    {
        const float* th = d_theta + ((size_t)(b * Nv + qbase + w * 32)) * 8;
        aA[0] = __float_as_uint(th[g * 8 + k4]);
        aA[1] = __float_as_uint(th[(g + 8) * 8 + k4]);
        aA[2] = __float_as_uint(th[g * 8 + k4 + 4]);
        aA[3] = __float_as_uint(th[(g + 8) * 8 + k4 + 4]);
        const float* tb = th + 128;
        aB[0] = __float_as_uint(tb[g * 8 + k4]);
        aB[1] = __float_as_uint(tb[(g + 8) * 8 + k4]);
        aB[2] = __float_as_uint(tb[g * 8 + k4 + 4]);
        aB[3] = __float_as_uint(tb[(g + 8) * 8 + k4 + 4]);
    }

    float oA[4][4], oB[4][4];
#pragma unroll
    for (int jt = 0; jt < 4; jt++)
#pragma unroll
        for (int i = 0; i < 4; i++) { oA[jt][i] = 0.f; oB[jt][i] = 0.f; }
    float oSA[4] = {0.f, 0.f, 0.f, 0.f};
    float oSB[4] = {0.f, 0.f, 0.f, 0.f};

    const char* phi_g = (const char*)(d_phi + (size_t)b * (Mv * 8));
    const char* gt_g = (const char*)(d_gTh + (size_t)b * (32 * Mv));

    // stage tile 0 into buffer 0 (128 threads: 2 phi + 4 gt each)
    {
        cpa16(sbase + tid * 16, phi_g + tid * 16);
        cpa16(sbase + (tid + 128) * 16, phi_g + (size_t)(tid + 128) * 16);
#pragma unroll
        for (int r = 0; r < 4; r++) {
            int i = tid + 128 * r;
            int row = i >> 4, c = i & 15;
            cpa16(sbase + 8192 + row * 272 + c * 16,
                  gt_g + (size_t)row * (Mv * 2) + c * 16);
        }
        CPA_COMMIT();
    }

#pragma unroll 1
    for (int mt = 0; mt < 8; mt++) {
        CPA_WAIT0();
        __syncthreads();

        int buf = mt & 1;
        if (mt < 7) {
            int nb = buf ^ 1;
            unsigned pbase = sbase + nb * 4096;
            unsigned gbase = sbase + 8192 + nb * 8704;
            const char* psrc = phi_g + (size_t)(mt + 1) * 4096;
            const char* gsrc = gt_g + (size_t)(mt + 1) * 256;
            cpa16(pbase + tid * 16, psrc + tid * 16);
            cpa16(pbase + (tid + 128) * 16, psrc + (size_t)(tid + 128) * 16);
#pragma unroll
            for (int r = 0; r < 4; r++) {
                int i = tid + 128 * r;
                int row = i >> 4, c = i & 15;
                cpa16(gbase + row * 272 + c * 16,
                      gsrc + (size_t)row * (Mv * 2) + c * 16);
            }
            CPA_COMMIT();
        }

        const float* phi_b = (const float*)(smraw + buf * 4096);
        unsigned gt_lane = sbase + 8192 + buf * 8704 + (unsigned)l * 272;

#pragma unroll
        for (int ms = 0; ms < 8; ms++) {
            int m0 = ms * 16;
            // g B-frags first (latency hidden under QK/ex2 chain)
            unsigned bg0[4], bg1[4];
            LDSM4(bg0, gt_lane + ms * 32);
            LDSM4(bg1, gt_lane + ms * 32 + 16);

            float2 bb0 = *(const float2*)&phi_b[(m0 + g) * 8 + k4 * 2];
            float2 bb1 = *(const float2*)&phi_b[(m0 + 8 + g) * 8 + k4 * 2];
            unsigned u0 = __float_as_uint(bb0.x), u1 = __float_as_uint(bb0.y);
            unsigned u2 = __float_as_uint(bb1.x), u3 = __float_as_uint(bb1.y);

            float sA0[4], sA1[4], sB0[4], sB1[4];
            mma_qk(sA0, aA, u0, u1);
            mma_qk(sA1, aA, u2, u3);
            mma_qk(sB0, aB, u0, u1);
            mma_qk(sB1, aB, u2, u3);

            unsigned paA[4], paB[4];
            paA[0] = ex2_f16x2(cvt_f16x2(sA0[1], sA0[0]));
            paA[1] = ex2_f16x2(cvt_f16x2(sA0[3], sA0[2]));
            paA[2] = ex2_f16x2(cvt_f16x2(sA1[1], sA1[0]));
            paA[3] = ex2_f16x2(cvt_f16x2(sA1[3], sA1[2]));
            paB[0] = ex2_f16x2(cvt_f16x2(sB0[1], sB0[0]));
            paB[1] = ex2_f16x2(cvt_f16x2(sB0[3], sB0[2]));
            paB[2] = ex2_f16x2(cvt_f16x2(sB1[1], sB1[0]));
            paB[3] = ex2_f16x2(cvt_f16x2(sB1[3], sB1[2]));

#pragma unroll
            for (int jt = 0; jt < 4; jt++) {
                mma_pv(oA[jt], paA, bg0[jt], bg1[jt]);
                mma_pv(oB[jt], paB, bg0[jt], bg1[jt]);
            }
            mma_pv(oSA, paA, ONES_F16X2, ONES_F16X2);
            mma_pv(oSB, paB, ONES_F16X2, ONES_F16X2);
        }
    }

    __syncthreads();   // tile compute done; overlay epilogue arrays
    float* o_s = (float*)smraw;                 // [128][32]
    float* wa_s = (float*)(smraw + 16384);      // [2048]
    float* lsum_s = (float*)(smraw + 24576);    // [128]

    if (k4 == 0) {
        lsum_s[w * 32 + g] = oSA[0];
        lsum_s[w * 32 + g + 8] = oSA[2];
        lsum_s[w * 32 + 16 + g] = oSB[0];
        lsum_s[w * 32 + 16 + g + 8] = oSB[2];
    }
    {
        int q0 = w * 32;
#pragma unroll
        for (int jt = 0; jt < 4; jt++) {
            int jc = jt * 8 + 2 * k4;
            *(float2*)&o_s[(q0 + g) * 32 + jc] = make_float2(oA[jt][0], oA[jt][1]);
            *(float2*)&o_s[(q0 + g + 8) * 32 + jc] = make_float2(oA[jt][2], oA[jt][3]);
            *(float2*)&o_s[(q0 + 16 + g) * 32 + jc] = make_float2(oB[jt][0], oB[jt][1]);
            *(float2*)&o_s[(q0 + 16 + g + 8) * 32 + jc] = make_float2(oB[jt][2], oB[jt][3]);
        }
    }
    for (int i = tid; i < 2048; i += 128) wa_s[i] = Wattn[i];
    __syncthreads();

    // epilogue: 1 thread per query, all 64 output channels
    int q = tid;
    float av[32];
    {
        const float4* os = (const float4*)&o_s[q * 32];
        float inv = sigma[0] / lsum_s[q];
#pragma unroll
        for (int i = 0; i < 8; i++) {
            float4 v = os[i];
            av[i * 4 + 0] = v.x * inv; av[i * 4 + 1] = v.y * inv;
            av[i * 4 + 2] = v.z * inv; av[i * 4 + 3] = v.w * inv;
        }
    }
    ULL acc[16];
#pragma unroll
    for (int i = 0; i < 16; i++) acc[i] = f2_pack(av[2 * i], av[2 * i + 1]);

    int n = qbase + q;
    const float* xp = x + ((size_t)b * Cv) * Nv + n;
    float* op = out + ((size_t)b * Cv) * Nv + n;
    const ulonglong2* wa_u = (const ulonglong2*)wa_s;
#pragma unroll 4
    for (int co = 0; co < 64; co++) {
        const ulonglong2* wr = wa_u + (size_t)co * 8;
        ULL d2 = 0ULL;
#pragma unroll
        for (int jj = 0; jj < 8; jj++) {
            ulonglong2 wv = wr[jj];
            d2 = f2_fma(acc[jj * 2 + 0], wv.x, d2);
            d2 = f2_fma(acc[jj * 2 + 1], wv.y, d2);
        }
        float2 df = f2_unpack(d2);
        op[(size_t)co * Nv] = xp[(size_t)co * Nv] + (df.x + df.y);
    }
}

// ======================================================================
// launch
// ======================================================================
extern "C" void kernel_launch(void* const* d_in, const int* in_sizes, int n_in,
                              void* d_out, int out_size) {
    const float* x     = (const float*)d_in[0];
    const float* Wth   = (const float*)d_in[1];
    const float* Wphi  = (const float*)d_in[2];
    const float* Wg    = (const float*)d_in[3];
    const float* Wattn = (const float*)d_in[4];
    const float* sigma = (const float*)d_in[5];
    float* out = (float*)d_out;

    prep_kernel<<<dim3(8, Bv), 256>>>(x, Wth, Wphi, Wg);
    attn_kernel<<<dim3(Nv / 128, Bv), 128>>>(x, Wattn, sigma, out);
}